// round 4
// baseline (speedup 1.0000x reference)
#include <cuda_runtime.h>
#include <cuda_fp16.h>
#include <cstdint>
#include <cstddef>

#define B_ 256
#define T_ 512
#define H_ 256
#define I_ 64
#define CSZ 8
#define MR 16
#define NLOC 128

// ---------------- device scratch (no runtime allocation allowed) ----------------
__device__ uint4  g_h1[(size_t)B_ * T_ * H_ / 8];       // layer-0 output seq, fp16, 64 MB
__device__ float  g_h2last[B_ * H_];                    // final h of layer 1
__device__ uint4  g_w0[(size_t)CSZ * NLOC * 320 / 8];   // packed fp16 weights, layer 0
__device__ uint4  g_w1[(size_t)CSZ * NLOC * 512 / 8];   // packed fp16 weights, layer 1
__device__ float  g_bias0[CSZ * NLOC];
__device__ float  g_bias1[CSZ * NLOC];

// ---------------- helpers ----------------
__device__ __forceinline__ unsigned su32(const void* p) {
    unsigned a;
    asm("{ .reg .u64 t; cvta.to.shared.u64 t, %1; cvt.u32.u64 %0, t; }" : "=r"(a) : "l"(p));
    return a;
}
__device__ __forceinline__ float sigm(float x) {
    return __fdividef(1.f, 1.f + __expf(-x));
}
__device__ __forceinline__ float tanh_acc(float x) {
    x = fminf(fmaxf(x, -15.f), 15.f);
    float e = __expf(2.f * x);
    return __fdividef(e - 1.f, e + 1.f);
}

// ---------------- weight prep: fp32 -> packed fp16 slices ----------------
// Local row l of rank r: gate block b = l>>5, h-col = r*32 + (l&31),
// global gate row grow = b*256 + r*32 + (l&31).
// K layout: [0,256) = Whh row, [256,256+KIN) = Wih row.
__global__ void prep_kernel(const float* __restrict__ Wih0, const float* __restrict__ Whh0,
                            const float* __restrict__ bih0, const float* __restrict__ bhh0,
                            const float* __restrict__ Wih1, const float* __restrict__ Whh1,
                            const float* __restrict__ bih1, const float* __restrict__ bhh1) {
    int blk = blockIdx.x;
    if (blk < 1024) {
        int r = blk >> 7, l = blk & 127;
        int grow = (l >> 5) * H_ + r * 32 + (l & 31);
        __half* dst = (__half*)g_w0 + (size_t)(r * NLOC + l) * 320;
        for (int k = threadIdx.x; k < 320; k += blockDim.x) {
            float v = (k < 256) ? Whh0[grow * H_ + k] : Wih0[grow * I_ + (k - 256)];
            dst[k] = __float2half_rn(v);
        }
        if (threadIdx.x == 0) g_bias0[r * NLOC + l] = bih0[grow] + bhh0[grow];
    } else {
        int bb = blk - 1024;
        int r = bb >> 7, l = bb & 127;
        int grow = (l >> 5) * H_ + r * 32 + (l & 31);
        __half* dst = (__half*)g_w1 + (size_t)(r * NLOC + l) * 512;
        for (int k = threadIdx.x; k < 512; k += blockDim.x) {
            float v = (k < 256) ? Whh1[grow * H_ + k] : Wih1[grow * H_ + (k - 256)];
            dst[k] = __float2half_rn(v);
        }
        if (threadIdx.x == 0) g_bias1[r * NLOC + l] = bih1[grow] + bhh1[grow];
    }
}

// ---------------- persistent LSTM layer kernel ----------------
// Cluster of 8 CTAs = one batch group of 16 rows. CTA rank r owns gate rows
// {b*256 + r*32 + j : b in 0..3, j in 0..31} and h-columns [r*32, r*32+32).
// mma formulation: D[16 gates x 8 batch] = W(16x16k, A-frag, registers) x Hin^T(16k x 8, B-frag).
template <int KIN, bool WRITE_SEQ>
__global__ void __launch_bounds__(256, 1) __cluster_dims__(CSZ, 1, 1)
lstm_kernel(const float* __restrict__ xin) {
    constexpr int K   = 256 + KIN;
    constexpr int KT  = K / 16;           // k-tiles
    constexpr int KP  = K + 8;            // padded W row stride (halves)
    constexpr int KPB = KP * 2;
    constexpr int HPB = 264 * 2;          // h row stride bytes (256+8 halves)
    constexpr int XPB = (KIN + 8) * 2;    // x row stride bytes
    constexpr int HBUF = MR * HPB;        // one h buffer = 8448 B

    extern __shared__ __align__(16) char smem[];
    char*  sW    = smem;                                   // NLOC*KPB
    char*  sH    = sW + NLOC * KPB;                        // 2 buffers
    char*  sX    = sH + 2 * HBUF;                          // MR*XPB
    float* sG    = (float*)(sX + MR * XPB);                // NLOC x 17
    float* sBias = sG + NLOC * 17;                         // NLOC

    const int tid  = threadIdx.x;
    const int wid  = tid >> 5;
    const int lane = tid & 31;
    unsigned rank;
    asm("mov.u32 %0, %%cluster_ctarank;" : "=r"(rank));
    const int bm0 = (blockIdx.x >> 3) * MR;   // first batch row of this group

    // ---- stage weights to SMEM ----
    {
        const uint4* src = (KIN == 64 ? g_w0 : g_w1) + (size_t)rank * NLOC * K / 8;
        constexpr int ROWV = K / 8;  // uint4 per row
        for (int i = tid; i < NLOC * ROWV; i += 256) {
            int l = i / ROWV, c = i % ROWV;
            *(uint4*)(sW + l * KPB + c * 16) = src[i];
        }
    }
    // zero both h buffers (h_{-1}=0; buffer 1 fully overwritten each step anyway)
    for (int i = tid; i < 2 * HBUF / 4; i += 256) ((unsigned*)sH)[i] = 0u;
    if (tid < NLOC) sBias[tid] = (KIN == 64 ? g_bias0 : g_bias1)[rank * NLOC + tid];
    __syncthreads();

    // ---- load W fragments into registers (A-frags, ldmatrix.x4) ----
    uint32_t wreg[KT][4];
    {
        unsigned base = su32(sW);
        unsigned rb = base + (unsigned)(wid * 16 + (lane & 15)) * KPB + ((lane & 16) ? 16u : 0u);
#pragma unroll
        for (int kt = 0; kt < KT; kt++) {
            unsigned a = rb + kt * 32;
            asm volatile("ldmatrix.sync.aligned.m8n8.x4.shared.b16 {%0,%1,%2,%3}, [%4];"
                         : "=r"(wreg[kt][0]), "=r"(wreg[kt][1]), "=r"(wreg[kt][2]), "=r"(wreg[kt][3])
                         : "r"(a));
        }
    }

    // per-thread activation mapping: m_act = batch row, handles h-cols 2*jj, 2*jj+1
    const int m_act = tid >> 4, jj = tid & 15;
    float c0 = 0.f, c1 = 0.f;

    const unsigned sHu = su32(sH);
    const unsigned sXu = su32(sX);
    // ldmatrix B-frag per-lane offsets (lanes 16-31 addresses unused by .x2 but valid)
    const unsigned hoffL = (unsigned)((lane & 7) * HPB) + ((lane & 8) ? 16u : 0u);
    const unsigned xoffL = (unsigned)((lane & 7) * XPB) + ((lane & 8) ? 16u : 0u);
    // DSMEM h-write offset within a buffer for this thread
    const unsigned hw_off = (unsigned)(m_act * HPB + (rank * 32 + 2 * jj) * 2);
    const int gid = lane >> 2, ctid = lane & 3;

    for (int t = 0; t < T_; t++) {
        const int rbuf = t & 1, wbuf = rbuf ^ 1;

        // ---- phase 1: load x_t into sX ----
        if (KIN == 64) {
            int m = tid >> 4, k4 = (tid & 15) * 4;
            float4 v = *(const float4*)&xin[((size_t)(bm0 + m) * T_ + t) * I_ + k4];
            __half2* d = (__half2*)(sX + m * XPB + k4 * 2);
            d[0] = __floats2half2_rn(v.x, v.y);
            d[1] = __floats2half2_rn(v.z, v.w);
        } else {
            int m = tid >> 4, c = tid & 15;
            const uint4* srow = g_h1 + ((size_t)(bm0 + m) * T_ + t) * 32;
            *(uint4*)(sX + m * XPB + c * 16)        = srow[c];
            *(uint4*)(sX + m * XPB + (c + 16) * 16) = srow[c + 16];
        }
        __syncthreads();

        // ---- phase 3: mma over all k-tiles, two n-tiles (batch 0-7, 8-15) ----
        float accA[2][4] = {{0.f,0.f,0.f,0.f},{0.f,0.f,0.f,0.f}};
        float accB[2][4] = {{0.f,0.f,0.f,0.f},{0.f,0.f,0.f,0.f}};
#pragma unroll
        for (int nt = 0; nt < 2; nt++) {
            unsigned hb = sHu + (unsigned)rbuf * HBUF + (unsigned)(nt * 8) * HPB + hoffL;
            unsigned xb = sXu + (unsigned)(nt * 8) * XPB + xoffL;
#pragma unroll
            for (int kt = 0; kt < KT; kt++) {
                unsigned a = (kt < 16) ? (hb + kt * 32) : (xb + (kt - 16) * 32);
                uint32_t b0, b1;
                asm volatile("ldmatrix.sync.aligned.m8n8.x2.shared.b16 {%0,%1}, [%2];"
                             : "=r"(b0), "=r"(b1) : "r"(a));
                float* acc = (kt & 1) ? accB[nt] : accA[nt];
                asm volatile(
                    "mma.sync.aligned.m16n8k16.row.col.f32.f16.f16.f32 "
                    "{%0,%1,%2,%3}, {%4,%5,%6,%7}, {%8,%9}, {%0,%1,%2,%3};"
                    : "+f"(acc[0]), "+f"(acc[1]), "+f"(acc[2]), "+f"(acc[3])
                    : "r"(wreg[kt][0]), "r"(wreg[kt][1]), "r"(wreg[kt][2]), "r"(wreg[kt][3]),
                      "r"(b0), "r"(b1));
            }
        }

        // ---- phase 4: dump gate pre-activations to sG ----
#pragma unroll
        for (int nt = 0; nt < 2; nt++) {
            int col = nt * 8 + 2 * ctid;
            int row = wid * 16 + gid;
            sG[row * 17 + col]           = accA[nt][0] + accB[nt][0];
            sG[row * 17 + col + 1]       = accA[nt][1] + accB[nt][1];
            sG[(row + 8) * 17 + col]     = accA[nt][2] + accB[nt][2];
            sG[(row + 8) * 17 + col + 1] = accA[nt][3] + accB[nt][3];
        }
        __syncthreads();

        // ---- phase 5: LSTM cell math + h broadcast ----
        {
            int j0 = 2 * jj, j1 = j0 + 1;
            float gi = sG[(0  + j0) * 17 + m_act] + sBias[0  + j0];
            float gf = sG[(32 + j0) * 17 + m_act] + sBias[32 + j0];
            float gg = sG[(64 + j0) * 17 + m_act] + sBias[64 + j0];
            float go = sG[(96 + j0) * 17 + m_act] + sBias[96 + j0];
            c0 = sigm(gf) * c0 + sigm(gi) * tanh_acc(gg);
            float h0 = sigm(go) * tanh_acc(c0);

            gi = sG[(0  + j1) * 17 + m_act] + sBias[0  + j1];
            gf = sG[(32 + j1) * 17 + m_act] + sBias[32 + j1];
            gg = sG[(64 + j1) * 17 + m_act] + sBias[64 + j1];
            go = sG[(96 + j1) * 17 + m_act] + sBias[96 + j1];
            c1 = sigm(gf) * c1 + sigm(gi) * tanh_acc(gg);
            float h1 = sigm(go) * tanh_acc(c1);

            __half2 hp = __floats2half2_rn(h0, h1);
            unsigned hv = *(unsigned*)&hp;
            unsigned dsta = sHu + (unsigned)wbuf * HBUF + hw_off;
#pragma unroll
            for (int rr = 0; rr < CSZ; rr++) {
                unsigned ra;
                asm volatile("mapa.shared::cluster.u32 %0, %1, %2;" : "=r"(ra) : "r"(dsta), "r"(rr));
                asm volatile("st.shared::cluster.u32 [%0], %1;" :: "r"(ra), "r"(hv) : "memory");
            }
            if (WRITE_SEQ) {
                size_t off = ((size_t)(bm0 + m_act) * T_ + t) * H_ + rank * 32 + j0;
                *(uint32_t*)((__half*)g_h1 + off) = hv;
            } else if (t == T_ - 1) {
                g_h2last[(bm0 + m_act) * H_ + rank * 32 + j0] = h0;
                g_h2last[(bm0 + m_act) * H_ + rank * 32 + j1] = h1;
            }
        }

        // ---- phase 6: cluster barrier (orders DSMEM h writes for next step) ----
        asm volatile("barrier.cluster.arrive.aligned;" ::: "memory");
        asm volatile("barrier.cluster.wait.aligned;" ::: "memory");
    }
}

// ---------------- FC head: y = (h2last @ W1^T + b1) @ W2^T + b2 ----------------
__global__ void head_kernel(const float* __restrict__ W1, const float* __restrict__ b1,
                            const float* __restrict__ W2, const float* __restrict__ b2,
                            float* __restrict__ out) {
    __shared__ float sLast[H_];
    __shared__ float sZ[5 * H_];
    int b = blockIdx.x, tid = threadIdx.x;
    sLast[tid] = g_h2last[b * H_ + tid];
    __syncthreads();
#pragma unroll
    for (int q = 0; q < 5; q++) {
        int j = q * 256 + tid;
        const float* wr = W1 + (size_t)j * H_;
        float acc = 0.f;
#pragma unroll 8
        for (int k = 0; k < H_; k += 4) {
            float4 w = *(const float4*)&wr[k];
            acc += w.x * sLast[k] + w.y * sLast[k + 1] + w.z * sLast[k + 2] + w.w * sLast[k + 3];
        }
        sZ[j] = acc + b1[j];
    }
    __syncthreads();
    int w = tid >> 5, l = tid & 31;
    if (w < 4) {
        float acc = 0.f;
        for (int i = l; i < 1280; i += 32) acc += sZ[i] * W2[w * 1280 + i];
#pragma unroll
        for (int s = 16; s; s >>= 1) acc += __shfl_xor_sync(0xffffffffu, acc, s);
        if (l == 0) out[b * 4 + w] = acc + b2[w];
    }
}

// ---------------- launch ----------------
extern "C" void kernel_launch(void* const* d_in, const int* in_sizes, int n_in,
                              void* d_out, int out_size) {
    const float* x    = (const float*)d_in[0];
    const float* Wih0 = (const float*)d_in[1];
    const float* Whh0 = (const float*)d_in[2];
    const float* bih0 = (const float*)d_in[3];
    const float* bhh0 = (const float*)d_in[4];
    const float* Wih1 = (const float*)d_in[5];
    const float* Whh1 = (const float*)d_in[6];
    const float* bih1 = (const float*)d_in[7];
    const float* bhh1 = (const float*)d_in[8];
    const float* W1   = (const float*)d_in[9];
    const float* b1   = (const float*)d_in[10];
    const float* W2   = (const float*)d_in[11];
    const float* b2   = (const float*)d_in[12];

    // SMEM: layer0 = 128*328*2 + 2*16*528 + 16*144 + 128*17*4 + 512 = 112384
    //       layer1 = 128*520*2 + 2*16*528 + 16*528 + 128*17*4 + 512 = 167680
    constexpr int SM0 = 112384;
    constexpr int SM1 = 167680;
    cudaFuncSetAttribute(lstm_kernel<64, true>,   cudaFuncAttributeMaxDynamicSharedMemorySize, SM0);
    cudaFuncSetAttribute(lstm_kernel<256, false>, cudaFuncAttributeMaxDynamicSharedMemorySize, SM1);

    prep_kernel<<<2048, 64>>>(Wih0, Whh0, bih0, bhh0, Wih1, Whh1, bih1, bhh1);
    lstm_kernel<64, true><<<128, 256, SM0>>>(x);
    lstm_kernel<256, false><<<128, 256, SM1>>>(x);
    head_kernel<<<256, 256>>>(W1, b1, W2, b2, (float*)d_out);
}

// round 5
// speedup vs baseline: 1.3060x; 1.3060x over previous
#include <cuda_runtime.h>
#include <cuda_fp16.h>
#include <cstdint>
#include <cstddef>

#define B_ 256
#define T_ 512
#define H_ 256
#define I_ 64
#define CSZ 8
#define MR 16
#define NLOC 128

// ---------------- device scratch (no runtime allocation allowed) ----------------
__device__ uint4  g_h1[(size_t)B_ * T_ * H_ / 8];       // layer-0 output seq, fp16, 64 MB
__device__ float  g_h2last[B_ * H_];                    // final h of layer 1
__device__ uint4  g_w0[(size_t)CSZ * NLOC * 320 / 8];   // packed fp16 weights, layer 0
__device__ uint4  g_w1[(size_t)CSZ * NLOC * 512 / 8];   // packed fp16 weights, layer 1
__device__ float  g_bias0[CSZ * NLOC];
__device__ float  g_bias1[CSZ * NLOC];

// ---------------- helpers ----------------
__device__ __forceinline__ unsigned su32(const void* p) {
    unsigned a;
    asm("{ .reg .u64 t; cvta.to.shared.u64 t, %1; cvt.u32.u64 %0, t; }" : "=r"(a) : "l"(p));
    return a;
}
__device__ __forceinline__ float tanhap(float x) {
    float y;
    asm("tanh.approx.f32 %0, %1;" : "=f"(y) : "f"(x));
    return y;
}
__device__ __forceinline__ float sigm(float x) {
    return fmaf(tanhap(0.5f * x), 0.5f, 0.5f);
}

// ---------------- weight prep: fp32 -> packed fp16 slices ----------------
__global__ void prep_kernel(const float* __restrict__ Wih0, const float* __restrict__ Whh0,
                            const float* __restrict__ bih0, const float* __restrict__ bhh0,
                            const float* __restrict__ Wih1, const float* __restrict__ Whh1,
                            const float* __restrict__ bih1, const float* __restrict__ bhh1) {
    int blk = blockIdx.x;
    if (blk < 1024) {
        int r = blk >> 7, l = blk & 127;
        int grow = (l >> 5) * H_ + r * 32 + (l & 31);
        __half* dst = (__half*)g_w0 + (size_t)(r * NLOC + l) * 320;
        for (int k = threadIdx.x; k < 320; k += blockDim.x) {
            float v = (k < 256) ? Whh0[grow * H_ + k] : Wih0[grow * I_ + (k - 256)];
            dst[k] = __float2half_rn(v);
        }
        if (threadIdx.x == 0) g_bias0[r * NLOC + l] = bih0[grow] + bhh0[grow];
    } else {
        int bb = blk - 1024;
        int r = bb >> 7, l = bb & 127;
        int grow = (l >> 5) * H_ + r * 32 + (l & 31);
        __half* dst = (__half*)g_w1 + (size_t)(r * NLOC + l) * 512;
        for (int k = threadIdx.x; k < 512; k += blockDim.x) {
            float v = (k < 256) ? Whh1[grow * H_ + k] : Wih1[grow * H_ + (k - 256)];
            dst[k] = __float2half_rn(v);
        }
        if (threadIdx.x == 0) g_bias1[r * NLOC + l] = bih1[grow] + bhh1[grow];
    }
}

// ---------------- persistent LSTM layer kernel ----------------
// Cluster of 8 CTAs = one batch group of 16 rows. Rank r owns gate rows
// {b*256 + r*32 + j} and h-cols [r*32, r*32+32). Weights live in registers
// as mma A-frags; per step: mma -> sG exchange -> cell math -> DSMEM h bcast.
// Software-pipelined: x_{t+1} LDG issued before step-t mma; single CTA sync
// per step; cluster barrier doubles as the second sync.
template <int KIN, bool WRITE_SEQ>
__global__ void __launch_bounds__(256, 1) __cluster_dims__(CSZ, 1, 1)
lstm_kernel(const float* __restrict__ xin) {
    constexpr int K   = 256 + KIN;
    constexpr int KT  = K / 16;
    constexpr int KP  = K + 8;
    constexpr int KPB = KP * 2;
    constexpr int HPB = 264 * 2;
    constexpr int XPB = (KIN + 8) * 2;
    constexpr int HBUF = MR * HPB;

    extern __shared__ __align__(16) char smem[];
    char*  sW    = smem;
    char*  sH    = sW + NLOC * KPB;
    char*  sX    = sH + 2 * HBUF;
    float* sG    = (float*)(sX + MR * XPB);
    float* sBias = sG + NLOC * 17;

    const int tid  = threadIdx.x;
    const int wid  = tid >> 5;
    const int lane = tid & 31;
    unsigned rank;
    asm("mov.u32 %0, %%cluster_ctarank;" : "=r"(rank));
    const int bm0 = (blockIdx.x >> 3) * MR;

    // ---- stage weights to SMEM ----
    {
        const uint4* src = (KIN == 64 ? g_w0 : g_w1) + (size_t)rank * NLOC * K / 8;
        constexpr int ROWV = K / 8;
        for (int i = tid; i < NLOC * ROWV; i += 256) {
            int l = i / ROWV, c = i % ROWV;
            *(uint4*)(sW + l * KPB + c * 16) = src[i];
        }
    }
    for (int i = tid; i < 2 * HBUF / 4; i += 256) ((unsigned*)sH)[i] = 0u;
    if (tid < NLOC) sBias[tid] = (KIN == 64 ? g_bias0 : g_bias1)[rank * NLOC + tid];
    __syncthreads();

    // ---- load W fragments into registers ----
    uint32_t wreg[KT][4];
    {
        unsigned base = su32(sW);
        unsigned rb = base + (unsigned)(wid * 16 + (lane & 15)) * KPB + ((lane & 16) ? 16u : 0u);
#pragma unroll
        for (int kt = 0; kt < KT; kt++) {
            unsigned a = rb + kt * 32;
            asm volatile("ldmatrix.sync.aligned.m8n8.x4.shared.b16 {%0,%1,%2,%3}, [%4];"
                         : "=r"(wreg[kt][0]), "=r"(wreg[kt][1]), "=r"(wreg[kt][2]), "=r"(wreg[kt][3])
                         : "r"(a));
        }
    }

    const int m_act = tid >> 4, jj = tid & 15;
    float c0 = 0.f, c1 = 0.f;

    const unsigned sHu = su32(sH);
    const unsigned sXu = su32(sX);
    const unsigned hoffL = (unsigned)((lane & 7) * HPB) + ((lane & 8) ? 16u : 0u);
    const unsigned xoffL = (unsigned)((lane & 7) * XPB) + ((lane & 8) ? 16u : 0u);
    const int gid = lane >> 2, ctid = lane & 3;

    // Precompute remote DSMEM base addresses for the h broadcast (wbuf offset added per step)
    const unsigned hw_off = (unsigned)(m_act * HPB + (rank * 32 + 2 * jj) * 2);
    unsigned rbase[CSZ];
#pragma unroll
    for (int rr = 0; rr < CSZ; rr++) {
        asm volatile("mapa.shared::cluster.u32 %0, %1, %2;"
                     : "=r"(rbase[rr]) : "r"(sHu + hw_off), "r"(rr));
    }

    // x staging mapping for this thread
    const int mx = tid >> 4, cx = tid & 15;

    // ---- preamble: prefetch t=0, stage into sX, then cluster-sync ----
    float4 xf;            // layer-0 prefetch
    uint4  p0, p1;        // layer-1 prefetch
    if (KIN == 64) {
        xf = *(const float4*)&xin[((size_t)(bm0 + mx) * T_ + 0) * I_ + cx * 4];
        __half2* d = (__half2*)(sX + mx * XPB + cx * 8);
        d[0] = __floats2half2_rn(xf.x, xf.y);
        d[1] = __floats2half2_rn(xf.z, xf.w);
    } else {
        const uint4* srow = g_h1 + ((size_t)(bm0 + mx) * T_ + 0) * 32;
        p0 = srow[cx]; p1 = srow[cx + 16];
        *(uint4*)(sX + mx * XPB + cx * 16)        = p0;
        *(uint4*)(sX + mx * XPB + (cx + 16) * 16) = p1;
    }
    // init barrier: closes zero-fill vs remote-store race AND publishes sX
    asm volatile("barrier.cluster.arrive.aligned;" ::: "memory");
    asm volatile("barrier.cluster.wait.aligned;" ::: "memory");

    for (int t = 0; t < T_; t++) {
        const int rbuf = t & 1, wbuf = rbuf ^ 1;
        const int tn = (t + 1 < T_) ? t + 1 : t;

        // ---- prefetch x_{t+1} into registers (latency hidden under mma) ----
        if (KIN == 64) {
            xf = *(const float4*)&xin[((size_t)(bm0 + mx) * T_ + tn) * I_ + cx * 4];
        } else {
            const uint4* srow = g_h1 + ((size_t)(bm0 + mx) * T_ + tn) * 32;
            p0 = srow[cx]; p1 = srow[cx + 16];
        }

        // ---- mma over all k-tiles, two n-tiles ----
        float accA[2][4] = {{0.f,0.f,0.f,0.f},{0.f,0.f,0.f,0.f}};
        float accB[2][4] = {{0.f,0.f,0.f,0.f},{0.f,0.f,0.f,0.f}};
#pragma unroll
        for (int nt = 0; nt < 2; nt++) {
            unsigned hb = sHu + (unsigned)rbuf * HBUF + (unsigned)(nt * 8) * HPB + hoffL;
            unsigned xb = sXu + (unsigned)(nt * 8) * XPB + xoffL;
#pragma unroll
            for (int kt = 0; kt < KT; kt++) {
                unsigned a = (kt < 16) ? (hb + kt * 32) : (xb + (kt - 16) * 32);
                uint32_t b0, b1;
                asm volatile("ldmatrix.sync.aligned.m8n8.x2.shared.b16 {%0,%1}, [%2];"
                             : "=r"(b0), "=r"(b1) : "r"(a));
                float* acc = (kt & 1) ? accB[nt] : accA[nt];
                asm volatile(
                    "mma.sync.aligned.m16n8k16.row.col.f32.f16.f16.f32 "
                    "{%0,%1,%2,%3}, {%4,%5,%6,%7}, {%8,%9}, {%0,%1,%2,%3};"
                    : "+f"(acc[0]), "+f"(acc[1]), "+f"(acc[2]), "+f"(acc[3])
                    : "r"(wreg[kt][0]), "r"(wreg[kt][1]), "r"(wreg[kt][2]), "r"(wreg[kt][3]),
                      "r"(b0), "r"(b1));
            }
        }

        // ---- dump gate pre-activations to sG (per-warp-private rows, no sync needed) ----
#pragma unroll
        for (int nt = 0; nt < 2; nt++) {
            int col = nt * 8 + 2 * ctid;
            int row = wid * 16 + gid;
            sG[row * 17 + col]           = accA[nt][0] + accB[nt][0];
            sG[row * 17 + col + 1]       = accA[nt][1] + accB[nt][1];
            sG[(row + 8) * 17 + col]     = accA[nt][2] + accB[nt][2];
            sG[(row + 8) * 17 + col + 1] = accA[nt][3] + accB[nt][3];
        }
        __syncthreads();   // sX/sH reads done + sG visible

        // ---- stage prefetched x_{t+1} into sX (published by end-of-step barrier) ----
        if (KIN == 64) {
            __half2* d = (__half2*)(sX + mx * XPB + cx * 8);
            d[0] = __floats2half2_rn(xf.x, xf.y);
            d[1] = __floats2half2_rn(xf.z, xf.w);
        } else {
            *(uint4*)(sX + mx * XPB + cx * 16)        = p0;
            *(uint4*)(sX + mx * XPB + (cx + 16) * 16) = p1;
        }

        // ---- LSTM cell math + h broadcast ----
        {
            int j0 = 2 * jj, j1 = j0 + 1;
            float gi = sG[(0  + j0) * 17 + m_act] + sBias[0  + j0];
            float gf = sG[(32 + j0) * 17 + m_act] + sBias[32 + j0];
            float gg = sG[(64 + j0) * 17 + m_act] + sBias[64 + j0];
            float go = sG[(96 + j0) * 17 + m_act] + sBias[96 + j0];
            c0 = sigm(gf) * c0 + sigm(gi) * tanhap(gg);
            float h0 = sigm(go) * tanhap(c0);

            gi = sG[(0  + j1) * 17 + m_act] + sBias[0  + j1];
            gf = sG[(32 + j1) * 17 + m_act] + sBias[32 + j1];
            gg = sG[(64 + j1) * 17 + m_act] + sBias[64 + j1];
            go = sG[(96 + j1) * 17 + m_act] + sBias[96 + j1];
            c1 = sigm(gf) * c1 + sigm(gi) * tanhap(gg);
            float h1 = sigm(go) * tanhap(c1);

            __half2 hp = __floats2half2_rn(h0, h1);
            unsigned hv = *(unsigned*)&hp;
            const unsigned woff = (unsigned)wbuf * HBUF;
#pragma unroll
            for (int rr = 0; rr < CSZ; rr++) {
                asm volatile("st.shared::cluster.u32 [%0], %1;"
                             :: "r"(rbase[rr] + woff), "r"(hv) : "memory");
            }
            if (WRITE_SEQ) {
                size_t off = ((size_t)(bm0 + m_act) * T_ + t) * H_ + rank * 32 + j0;
                *(uint32_t*)((__half*)g_h1 + off) = hv;
            } else if (t == T_ - 1) {
                g_h2last[(bm0 + m_act) * H_ + rank * 32 + j0] = h0;
                g_h2last[(bm0 + m_act) * H_ + rank * 32 + j1] = h1;
            }
        }

        // ---- cluster barrier: publishes DSMEM h (wbuf) and local sX for step t+1 ----
        asm volatile("barrier.cluster.arrive.aligned;" ::: "memory");
        asm volatile("barrier.cluster.wait.aligned;" ::: "memory");
    }
}

// ---------------- FC head: y = (h2last @ W1^T + b1) @ W2^T + b2 ----------------
// 4 batch rows per block: W1 traffic /4, 4 FMAs per W1 load.
__global__ void head_kernel(const float* __restrict__ W1, const float* __restrict__ b1,
                            const float* __restrict__ W2, const float* __restrict__ b2,
                            float* __restrict__ out) {
    __shared__ float sLast[4][H_];
    __shared__ float sZ[4][5 * H_ + 4];
    int b0 = blockIdx.x * 4, tid = threadIdx.x;
#pragma unroll
    for (int i = 0; i < 4; i++) sLast[i][tid] = g_h2last[(b0 + i) * H_ + tid];
    __syncthreads();
#pragma unroll
    for (int q = 0; q < 5; q++) {
        int j = q * 256 + tid;
        const float* wr = W1 + (size_t)j * H_;
        float a0 = 0.f, a1 = 0.f, a2 = 0.f, a3 = 0.f;
#pragma unroll 8
        for (int k = 0; k < H_; k += 4) {
            float4 w = *(const float4*)&wr[k];
            a0 += w.x * sLast[0][k] + w.y * sLast[0][k+1] + w.z * sLast[0][k+2] + w.w * sLast[0][k+3];
            a1 += w.x * sLast[1][k] + w.y * sLast[1][k+1] + w.z * sLast[1][k+2] + w.w * sLast[1][k+3];
            a2 += w.x * sLast[2][k] + w.y * sLast[2][k+1] + w.z * sLast[2][k+2] + w.w * sLast[2][k+3];
            a3 += w.x * sLast[3][k] + w.y * sLast[3][k+1] + w.z * sLast[3][k+2] + w.w * sLast[3][k+3];
        }
        float bb = b1[j];
        sZ[0][j] = a0 + bb; sZ[1][j] = a1 + bb; sZ[2][j] = a2 + bb; sZ[3][j] = a3 + bb;
    }
    __syncthreads();
    int w = tid >> 5, l = tid & 31;
    // 16 (batch,out) pairs over 8 warps: warp w handles pairs w and w+8
#pragma unroll
    for (int pp = 0; pp < 2; pp++) {
        int p = w + pp * 8;
        int b = p >> 2, o = p & 3;
        float acc = 0.f;
        for (int i = l; i < 1280; i += 32) acc += sZ[b][i] * W2[o * 1280 + i];
#pragma unroll
        for (int s = 16; s; s >>= 1) acc += __shfl_xor_sync(0xffffffffu, acc, s);
        if (l == 0) out[(b0 + b) * 4 + o] = acc + b2[o];
    }
}

// ---------------- launch ----------------
extern "C" void kernel_launch(void* const* d_in, const int* in_sizes, int n_in,
                              void* d_out, int out_size) {
    const float* x    = (const float*)d_in[0];
    const float* Wih0 = (const float*)d_in[1];
    const float* Whh0 = (const float*)d_in[2];
    const float* bih0 = (const float*)d_in[3];
    const float* bhh0 = (const float*)d_in[4];
    const float* Wih1 = (const float*)d_in[5];
    const float* Whh1 = (const float*)d_in[6];
    const float* bih1 = (const float*)d_in[7];
    const float* bhh1 = (const float*)d_in[8];
    const float* W1   = (const float*)d_in[9];
    const float* b1   = (const float*)d_in[10];
    const float* W2   = (const float*)d_in[11];
    const float* b2   = (const float*)d_in[12];

    constexpr int SM0 = 112384;
    constexpr int SM1 = 167680;
    cudaFuncSetAttribute(lstm_kernel<64, true>,   cudaFuncAttributeMaxDynamicSharedMemorySize, SM0);
    cudaFuncSetAttribute(lstm_kernel<256, false>, cudaFuncAttributeMaxDynamicSharedMemorySize, SM1);

    prep_kernel<<<2048, 64>>>(Wih0, Whh0, bih0, bhh0, Wih1, Whh1, bih1, bhh1);
    lstm_kernel<64, true><<<128, 256, SM0>>>(x);
    lstm_kernel<256, false><<<128, 256, SM1>>>(x);
    head_kernel<<<64, 256>>>(W1, b1, W2, b2, (float*)d_out);
}

// round 7
// speedup vs baseline: 1.3097x; 1.0028x over previous
#include <cuda_runtime.h>
#include <cuda_fp16.h>
#include <cstdint>
#include <cstddef>

#define B_ 256
#define T_ 512
#define H_ 256
#define I_ 64
#define CSZ 8
#define MR 16
#define NLOC 128
#define TCH 32   // time steps per xg-GEMM block

// ---------------- device scratch (no runtime allocation allowed) ----------------
__device__ uint4  g_h1[(size_t)B_ * T_ * H_ / 8];        // layer-0 output seq, fp16, 64 MB
__device__ float  g_h2last[B_ * H_];
__device__ __half g_whh0[CSZ * NLOC * 256];              // recurrent weights, rank-sliced
__device__ __half g_whh1[CSZ * NLOC * 256];
__device__ __half g_wih0[CSZ * NLOC * 64];               // input weights, rank-sliced
__device__ __half g_wih1[CSZ * NLOC * 256];
__device__ float  g_bias0[CSZ * NLOC];
__device__ float  g_bias1[CSZ * NLOC];
// Precomputed input-gate contributions (bias folded in): [cta(128), t(512), tid(256), 8]
__device__ float  g_xg0[(size_t)128 * 512 * 256 * 8];    // 536 MB
__device__ float  g_xg1[(size_t)128 * 512 * 256 * 8];    // 536 MB

// ---------------- helpers ----------------
__device__ __forceinline__ unsigned su32(const void* p) {
    unsigned a;
    asm("{ .reg .u64 t; cvta.to.shared.u64 t, %1; cvt.u32.u64 %0, t; }" : "=r"(a) : "l"(p));
    return a;
}
__device__ __forceinline__ float tanhap(float x) {
    float y;
    asm("tanh.approx.f32 %0, %1;" : "=f"(y) : "f"(x));
    return y;
}
__device__ __forceinline__ float sigm(float x) {
    return fmaf(tanhap(0.5f * x), 0.5f, 0.5f);
}
__device__ __forceinline__ void ldsm_x2(uint32_t& b0, uint32_t& b1, unsigned a) {
    asm volatile("ldmatrix.sync.aligned.m8n8.x2.shared.b16 {%0,%1}, [%2];"
                 : "=r"(b0), "=r"(b1) : "r"(a));
}
__device__ __forceinline__ void ldsm_x4(uint32_t* r, unsigned a) {
    asm volatile("ldmatrix.sync.aligned.m8n8.x4.shared.b16 {%0,%1,%2,%3}, [%4];"
                 : "=r"(r[0]), "=r"(r[1]), "=r"(r[2]), "=r"(r[3]) : "r"(a));
}
__device__ __forceinline__ void mma16816(float* acc, const uint32_t* a, uint32_t b0, uint32_t b1) {
    asm volatile(
        "mma.sync.aligned.m16n8k16.row.col.f32.f16.f16.f32 "
        "{%0,%1,%2,%3}, {%4,%5,%6,%7}, {%8,%9}, {%0,%1,%2,%3};"
        : "+f"(acc[0]), "+f"(acc[1]), "+f"(acc[2]), "+f"(acc[3])
        : "r"(a[0]), "r"(a[1]), "r"(a[2]), "r"(a[3]), "r"(b0), "r"(b1));
}

// ---------------- weight prep ----------------
// Local row l of rank r: gate g = l>>5, h-col = r*32 + (l&31), grow = g*256 + r*32 + (l&31).
__global__ void prep_kernel(const float* __restrict__ Wih0, const float* __restrict__ Whh0,
                            const float* __restrict__ bih0, const float* __restrict__ bhh0,
                            const float* __restrict__ Wih1, const float* __restrict__ Whh1,
                            const float* __restrict__ bih1, const float* __restrict__ bhh1) {
    int blk = blockIdx.x;
    int li = blk & 1023;
    int r = li >> 7, l = li & 127;
    int grow = (l >> 5) * H_ + r * 32 + (l & 31);
    if (blk < 1024) {
        for (int k = threadIdx.x; k < 256; k += blockDim.x)
            g_whh0[(r * NLOC + l) * 256 + k] = __float2half_rn(Whh0[grow * H_ + k]);
        for (int k = threadIdx.x; k < 64; k += blockDim.x)
            g_wih0[(r * NLOC + l) * 64 + k] = __float2half_rn(Wih0[grow * I_ + k]);
        if (threadIdx.x == 0) g_bias0[r * NLOC + l] = bih0[grow] + bhh0[grow];
    } else {
        for (int k = threadIdx.x; k < 256; k += blockDim.x) {
            g_whh1[(r * NLOC + l) * 256 + k] = __float2half_rn(Whh1[grow * H_ + k]);
            g_wih1[(r * NLOC + l) * 256 + k] = __float2half_rn(Wih1[grow * H_ + k]);
        }
        if (threadIdx.x == 0) g_bias1[r * NLOC + l] = bih1[grow] + bhh1[grow];
    }
}

// ---------------- time-parallel input GEMM: xg[cta,t,tid,0:8] = Wih slice @ in_t + bias ----
// grid (128 ctas, T/TCH). Same cta->(group,rank) mapping as the loop kernel.
template <int KK, bool XSRC>
__global__ void __launch_bounds__(256) xg_gemm(const float* __restrict__ xin) {
    constexpr int KT  = KK / 16;
    constexpr int KP  = KK + 8;
    constexpr int KPB = KP * 2;

    extern __shared__ __align__(16) char smem[];
    char*  sW    = smem;                       // 128 x KPB
    char*  sB    = sW + NLOC * KPB;            // 16 x KPB
    float* sG    = (float*)(sB + MR * KPB);    // 128 x 17
    float* sBias = sG + NLOC * 17;

    const int tid  = threadIdx.x;
    const int wid  = tid >> 5;
    const int lane = tid & 31;
    const int rank = blockIdx.x & 7;
    const int bm0  = (blockIdx.x >> 3) * MR;
    const int t0   = blockIdx.y * TCH;

    const __half* wsrc = (XSRC ? g_wih0 : g_wih1) + (size_t)rank * NLOC * KK;
    float*        out  = XSRC ? g_xg0 : g_xg1;
    {
        constexpr int ROWV = KK / 8;
        const uint4* src = (const uint4*)wsrc;
        for (int i = tid; i < NLOC * ROWV; i += 256) {
            int l = i / ROWV, c = i % ROWV;
            *(uint4*)(sW + l * KPB + c * 16) = src[i];
        }
    }
    if (tid < NLOC) sBias[tid] = (XSRC ? g_bias0 : g_bias1)[rank * NLOC + tid];
    __syncthreads();

    uint32_t wreg[KT][4];
    {
        unsigned rb = su32(sW) + (unsigned)(wid * 16 + (lane & 15)) * KPB + ((lane & 16) ? 16u : 0u);
#pragma unroll
        for (int kt = 0; kt < KT; kt++) ldsm_x4(wreg[kt], rb + kt * 32);
    }

    const unsigned sBu = su32(sB);
    const unsigned boffL = (unsigned)((lane & 7) * KPB) + ((lane & 8) ? 16u : 0u);
    const int gid = lane >> 2, ctid = lane & 3;
    const int m_act = tid >> 4, jj = tid & 15;
    const int mx = tid >> 4, cx = tid & 15;

    for (int tt = 0; tt < TCH; tt++) {
        const int t = t0 + tt;
        // stage B (16 x KK halves)
        if (XSRC) {
            float4 v = *(const float4*)&xin[((size_t)(bm0 + mx) * T_ + t) * I_ + cx * 4];
            __half2* d = (__half2*)(sB + mx * KPB + cx * 8);
            d[0] = __floats2half2_rn(v.x, v.y);
            d[1] = __floats2half2_rn(v.z, v.w);
        } else {
            const uint4* srow = g_h1 + ((size_t)(bm0 + mx) * T_ + t) * 32;
            *(uint4*)(sB + mx * KPB + cx * 32)      = srow[cx * 2];
            *(uint4*)(sB + mx * KPB + cx * 32 + 16) = srow[cx * 2 + 1];
        }
        __syncthreads();

        float accA[2][4] = {{0.f,0.f,0.f,0.f},{0.f,0.f,0.f,0.f}};
        float accB[2][4] = {{0.f,0.f,0.f,0.f},{0.f,0.f,0.f,0.f}};
#pragma unroll
        for (int nt = 0; nt < 2; nt++) {
            unsigned bb = sBu + (unsigned)(nt * 8) * KPB + boffL;
#pragma unroll
            for (int kt = 0; kt < KT; kt++) {
                uint32_t b0, b1;
                ldsm_x2(b0, b1, bb + kt * 32);
                mma16816((kt & 1) ? accB[nt] : accA[nt], wreg[kt], b0, b1);
            }
        }
#pragma unroll
        for (int nt = 0; nt < 2; nt++) {
            int col = nt * 8 + 2 * ctid;
            int row = wid * 16 + gid;
            sG[row * 17 + col]           = accA[nt][0] + accB[nt][0];
            sG[row * 17 + col + 1]       = accA[nt][1] + accB[nt][1];
            sG[(row + 8) * 17 + col]     = accA[nt][2] + accB[nt][2];
            sG[(row + 8) * 17 + col + 1] = accA[nt][3] + accB[nt][3];
        }
        __syncthreads();

        // epilogue: 8 gate pre-activations (+bias) per thread, coalesced
        {
            int j0 = 2 * jj, j1 = j0 + 1;
            float4 oA, oB;
            oA.x = sG[(0  + j0) * 17 + m_act] + sBias[0  + j0];
            oA.y = sG[(0  + j1) * 17 + m_act] + sBias[0  + j1];
            oA.z = sG[(32 + j0) * 17 + m_act] + sBias[32 + j0];
            oA.w = sG[(32 + j1) * 17 + m_act] + sBias[32 + j1];
            oB.x = sG[(64 + j0) * 17 + m_act] + sBias[64 + j0];
            oB.y = sG[(64 + j1) * 17 + m_act] + sBias[64 + j1];
            oB.z = sG[(96 + j0) * 17 + m_act] + sBias[96 + j0];
            oB.w = sG[(96 + j1) * 17 + m_act] + sBias[96 + j1];
            size_t base = (((size_t)blockIdx.x * T_ + t) * 256 + tid) * 8;
            *(float4*)&out[base]     = oA;
            *(float4*)&out[base + 4] = oB;
        }
        __syncthreads();
    }
}

// ---------------- persistent recurrent loop (K=256, h-only) ----------------
// Cluster of 8 CTAs = one batch group of 16 rows. Rank r owns gate rows
// {g*256 + r*32 + j} and h-cols [r*32, r*32+32). Input-gate terms precomputed in g_xg.
template <bool L0>
__global__ void __launch_bounds__(256, 1) __cluster_dims__(CSZ, 1, 1)
lstm_loop() {
    constexpr int KT  = 16;
    constexpr int KPB = 264 * 2;          // padded row stride bytes (256+8 halves)
    constexpr int HPB = KPB;
    constexpr int HBUF = MR * HPB;        // 8448 B

    extern __shared__ __align__(16) char smem[];
    char*  sW = smem;                     // 128 x KPB
    char*  sH = sW + NLOC * KPB;          // 2 buffers of 16 x HPB
    float* sG = (float*)(sH + 2 * HBUF);  // 128 x 17

    const int tid  = threadIdx.x;
    const int wid  = tid >> 5;
    const int lane = tid & 31;
    unsigned rank;
    asm("mov.u32 %0, %%cluster_ctarank;" : "=r"(rank));
    const int bm0 = (blockIdx.x >> 3) * MR;

    // stage recurrent weights
    {
        const uint4* src = (const uint4*)((L0 ? g_whh0 : g_whh1) + (size_t)rank * NLOC * 256);
        for (int i = tid; i < NLOC * 32; i += 256) {
            int l = i >> 5, c = i & 31;
            *(uint4*)(sW + l * KPB + c * 16) = src[i];
        }
    }
    for (int i = tid; i < 2 * HBUF / 4; i += 256) ((unsigned*)sH)[i] = 0u;
    __syncthreads();

    uint32_t wreg[KT][4];
    {
        unsigned rb = su32(sW) + (unsigned)(wid * 16 + (lane & 15)) * KPB + ((lane & 16) ? 16u : 0u);
#pragma unroll
        for (int kt = 0; kt < KT; kt++) ldsm_x4(wreg[kt], rb + kt * 32);
    }

    const int m_act = tid >> 4, jj = tid & 15;
    float c0 = 0.f, c1 = 0.f;

    const unsigned sHu = su32(sH);
    const unsigned hoffL = (unsigned)((lane & 7) * HPB) + ((lane & 8) ? 16u : 0u);
    const int gid = lane >> 2, ctid = lane & 3;

    // remote DSMEM bases for h broadcast
    const unsigned hw_off = (unsigned)(m_act * HPB + (rank * 32 + 2 * jj) * 2);
    unsigned rbase[CSZ];
#pragma unroll
    for (int rr = 0; rr < CSZ; rr++) {
        asm volatile("mapa.shared::cluster.u32 %0, %1, %2;"
                     : "=r"(rbase[rr]) : "r"(sHu + hw_off), "r"(rr));
    }

    // xg stream: 2 float4 per (t, thread)
    const float4* xg4 = (const float4*)(L0 ? g_xg0 : g_xg1);
    size_t xbase = ((size_t)blockIdx.x * T_) * 512 + tid * 2;   // float4 units
    float4 xgA = xg4[xbase], xgB = xg4[xbase + 1];

    // init barrier: closes zero-fill vs remote-store race
    asm volatile("barrier.cluster.arrive.aligned;" ::: "memory");
    asm volatile("barrier.cluster.wait.aligned;" ::: "memory");

    for (int t = 0; t < T_; t++) {
        const int rbuf = t & 1, wbuf = rbuf ^ 1;
        const int tn = (t + 1 < T_) ? t + 1 : t;

        // prefetch xg for t+1 (hidden under mma)
        float4 pA = xg4[xbase + (size_t)tn * 512];
        float4 pB = xg4[xbase + (size_t)tn * 512 + 1];

        // recurrent mma: D[128 x 16] += Whh_slice @ h^T
        float accA[2][4] = {{0.f,0.f,0.f,0.f},{0.f,0.f,0.f,0.f}};
        float accB[2][4] = {{0.f,0.f,0.f,0.f},{0.f,0.f,0.f,0.f}};
#pragma unroll
        for (int nt = 0; nt < 2; nt++) {
            unsigned hb = sHu + (unsigned)rbuf * HBUF + (unsigned)(nt * 8) * HPB + hoffL;
#pragma unroll
            for (int kt = 0; kt < KT; kt++) {
                uint32_t b0, b1;
                ldsm_x2(b0, b1, hb + kt * 32);
                mma16816((kt & 1) ? accB[nt] : accA[nt], wreg[kt], b0, b1);
            }
        }
#pragma unroll
        for (int nt = 0; nt < 2; nt++) {
            int col = nt * 8 + 2 * ctid;
            int row = wid * 16 + gid;
            sG[row * 17 + col]           = accA[nt][0] + accB[nt][0];
            sG[row * 17 + col + 1]       = accA[nt][1] + accB[nt][1];
            sG[(row + 8) * 17 + col]     = accA[nt][2] + accB[nt][2];
            sG[(row + 8) * 17 + col + 1] = accA[nt][3] + accB[nt][3];
        }
        __syncthreads();

        // cell math + h broadcast
        {
            int j0 = 2 * jj, j1 = j0 + 1;
            float gi0 = xgA.x + sG[(0  + j0) * 17 + m_act];
            float gi1 = xgA.y + sG[(0  + j1) * 17 + m_act];
            float gf0 = xgA.z + sG[(32 + j0) * 17 + m_act];
            float gf1 = xgA.w + sG[(32 + j1) * 17 + m_act];
            float gg0 = xgB.x + sG[(64 + j0) * 17 + m_act];
            float gg1 = xgB.y + sG[(64 + j1) * 17 + m_act];
            float go0 = xgB.z + sG[(96 + j0) * 17 + m_act];
            float go1 = xgB.w + sG[(96 + j1) * 17 + m_act];

            c0 = sigm(gf0) * c0 + sigm(gi0) * tanhap(gg0);
            float h0 = sigm(go0) * tanhap(c0);
            c1 = sigm(gf1) * c1 + sigm(gi1) * tanhap(gg1);
            float h1 = sigm(go1) * tanhap(c1);

            __half2 hp = __floats2half2_rn(h0, h1);
            unsigned hv = *(unsigned*)&hp;
            const unsigned woff = (unsigned)wbuf * HBUF;
#pragma unroll
            for (int rr = 0; rr < CSZ; rr++) {
                asm volatile("st.shared::cluster.u32 [%0], %1;"
                             :: "r"(rbase[rr] + woff), "r"(hv) : "memory");
            }
            if (L0) {
                size_t off = ((size_t)(bm0 + m_act) * T_ + t) * H_ + rank * 32 + j0;
                *(uint32_t*)((__half*)g_h1 + off) = hv;
            } else if (t == T_ - 1) {
                g_h2last[(bm0 + m_act) * H_ + rank * 32 + j0] = h0;
                g_h2last[(bm0 + m_act) * H_ + rank * 32 + j1] = h1;
            }
        }
        xgA = pA; xgB = pB;

        // publish DSMEM h for step t+1
        asm volatile("barrier.cluster.arrive.aligned;" ::: "memory");
        asm volatile("barrier.cluster.wait.aligned;" ::: "memory");
    }
}

// ---------------- FC head ----------------
__global__ void head_kernel(const float* __restrict__ W1, const float* __restrict__ b1,
                            const float* __restrict__ W2, const float* __restrict__ b2,
                            float* __restrict__ out) {
    __shared__ float sLast[4][H_];
    __shared__ float sZ[4][5 * H_ + 4];
    int b0 = blockIdx.x * 4, tid = threadIdx.x;
#pragma unroll
    for (int i = 0; i < 4; i++) sLast[i][tid] = g_h2last[(b0 + i) * H_ + tid];
    __syncthreads();
#pragma unroll
    for (int q = 0; q < 5; q++) {
        int j = q * 256 + tid;
        const float* wr = W1 + (size_t)j * H_;
        float a0 = 0.f, a1 = 0.f, a2 = 0.f, a3 = 0.f;
#pragma unroll 8
        for (int k = 0; k < H_; k += 4) {
            float4 w = *(const float4*)&wr[k];
            a0 += w.x * sLast[0][k] + w.y * sLast[0][k+1] + w.z * sLast[0][k+2] + w.w * sLast[0][k+3];
            a1 += w.x * sLast[1][k] + w.y * sLast[1][k+1] + w.z * sLast[1][k+2] + w.w * sLast[1][k+3];
            a2 += w.x * sLast[2][k] + w.y * sLast[2][k+1] + w.z * sLast[2][k+2] + w.w * sLast[2][k+3];
            a3 += w.x * sLast[3][k] + w.y * sLast[3][k+1] + w.z * sLast[3][k+2] + w.w * sLast[3][k+3];
        }
        float bb = b1[j];
        sZ[0][j] = a0 + bb; sZ[1][j] = a1 + bb; sZ[2][j] = a2 + bb; sZ[3][j] = a3 + bb;
    }
    __syncthreads();
    int w = tid >> 5, l = tid & 31;
#pragma unroll
    for (int pp = 0; pp < 2; pp++) {
        int p = w + pp * 8;
        int b = p >> 2, o = p & 3;
        float acc = 0.f;
        for (int i = l; i < 1280; i += 32) acc += sZ[b][i] * W2[o * 1280 + i];
#pragma unroll
        for (int s = 16; s; s >>= 1) acc += __shfl_xor_sync(0xffffffffu, acc, s);
        if (l == 0) out[(b0 + b) * 4 + o] = acc + b2[o];
    }
}

// ---------------- launch ----------------
extern "C" void kernel_launch(void* const* d_in, const int* in_sizes, int n_in,
                              void* d_out, int out_size) {
    const float* x    = (const float*)d_in[0];
    const float* Wih0 = (const float*)d_in[1];
    const float* Whh0 = (const float*)d_in[2];
    const float* bih0 = (const float*)d_in[3];
    const float* bhh0 = (const float*)d_in[4];
    const float* Wih1 = (const float*)d_in[5];
    const float* Whh1 = (const float*)d_in[6];
    const float* bih1 = (const float*)d_in[7];
    const float* bhh1 = (const float*)d_in[8];
    const float* W1   = (const float*)d_in[9];
    const float* b1   = (const float*)d_in[10];
    const float* W2   = (const float*)d_in[11];
    const float* b2   = (const float*)d_in[12];

    // smem sizes
    constexpr int KPB256 = 264 * 2, KPB64 = 72 * 2;
    constexpr int SMG0 = NLOC * KPB64  + MR * KPB64  + (NLOC * 17 + NLOC) * 4;  // ~30 KB
    constexpr int SMG1 = NLOC * KPB256 + MR * KPB256 + (NLOC * 17 + NLOC) * 4;  // ~85 KB
    constexpr int SML  = NLOC * KPB256 + 2 * MR * KPB256 + NLOC * 17 * 4;       // ~93 KB

    cudaFuncSetAttribute(xg_gemm<64, true>,   cudaFuncAttributeMaxDynamicSharedMemorySize, SMG0);
    cudaFuncSetAttribute(xg_gemm<256, false>, cudaFuncAttributeMaxDynamicSharedMemorySize, SMG1);
    cudaFuncSetAttribute(lstm_loop<true>,     cudaFuncAttributeMaxDynamicSharedMemorySize, SML);
    cudaFuncSetAttribute(lstm_loop<false>,    cudaFuncAttributeMaxDynamicSharedMemorySize, SML);

    prep_kernel<<<2048, 64>>>(Wih0, Whh0, bih0, bhh0, Wih1, Whh1, bih1, bhh1);
    xg_gemm<64, true><<<dim3(128, T_ / TCH), 256, SMG0>>>(x);
    lstm_loop<true><<<128, 256, SML>>>();
    xg_gemm<256, false><<<dim3(128, T_ / TCH), 256, SMG1>>>(x);
    lstm_loop<false><<<128, 256, SML>>>();
    head_kernel<<<64, 256>>>(W1, b1, W2, b2, (float*)d_out);
}

// round 9
// speedup vs baseline: 1.4994x; 1.1449x over previous
#include <cuda_runtime.h>
#include <cuda_fp16.h>
#include <cstdint>
#include <cstddef>

#define B_ 256
#define T_ 512
#define H_ 256
#define I_ 64
#define CSZ 8
#define MR 16
#define NLOC 128
#define TCH 32

// ---------------- device scratch ----------------
__device__ float  g_h2last[B_ * H_];
__device__ __half g_whh0[CSZ * NLOC * 256];    // L0 recurrent weights, rank-sliced
__device__ __half g_w1cat[CSZ * NLOC * 512];   // L1 [Whh1|Wih1] rows, rank-sliced
__device__ __half g_wih0[CSZ * NLOC * 64];
__device__ float  g_bias0[CSZ * NLOC];
__device__ float  g_bias1[CSZ * NLOC];
// Precomputed L0 input-gate terms (bias folded): [cta(128), t(512), tid(256), 8]
__device__ float  g_xg0[(size_t)128 * 512 * 256 * 8];

// ---------------- helpers ----------------
__device__ __forceinline__ unsigned su32(const void* p) {
    unsigned a;
    asm("{ .reg .u64 t; cvta.to.shared.u64 t, %1; cvt.u32.u64 %0, t; }" : "=r"(a) : "l"(p));
    return a;
}
__device__ __forceinline__ float tanhap(float x) {
    float y;
    asm("tanh.approx.f32 %0, %1;" : "=f"(y) : "f"(x));
    return y;
}
__device__ __forceinline__ float sigm(float x) {
    return fmaf(tanhap(0.5f * x), 0.5f, 0.5f);
}
__device__ __forceinline__ void ldsm_x2(uint32_t& b0, uint32_t& b1, unsigned a) {
    asm volatile("ldmatrix.sync.aligned.m8n8.x2.shared.b16 {%0,%1}, [%2];"
                 : "=r"(b0), "=r"(b1) : "r"(a));
}
__device__ __forceinline__ void ldsm_x4(uint32_t* r, unsigned a) {
    asm volatile("ldmatrix.sync.aligned.m8n8.x4.shared.b16 {%0,%1,%2,%3}, [%4];"
                 : "=r"(r[0]), "=r"(r[1]), "=r"(r[2]), "=r"(r[3]) : "r"(a));
}
__device__ __forceinline__ void mma16816(float* acc, const uint32_t* a, uint32_t b0, uint32_t b1) {
    asm volatile(
        "mma.sync.aligned.m16n8k16.row.col.f32.f16.f16.f32 "
        "{%0,%1,%2,%3}, {%4,%5,%6,%7}, {%8,%9}, {%0,%1,%2,%3};"
        : "+f"(acc[0]), "+f"(acc[1]), "+f"(acc[2]), "+f"(acc[3])
        : "r"(a[0]), "r"(a[1]), "r"(a[2]), "r"(a[3]), "r"(b0), "r"(b1));
}

// ---------------- weight prep ----------------
// Local row l of rank r: gate g = l>>5, h-col = r*32 + (l&31), grow = g*256 + r*32 + (l&31).
__global__ void prep_kernel(const float* __restrict__ Wih0, const float* __restrict__ Whh0,
                            const float* __restrict__ bih0, const float* __restrict__ bhh0,
                            const float* __restrict__ Wih1, const float* __restrict__ Whh1,
                            const float* __restrict__ bih1, const float* __restrict__ bhh1) {
    int blk = blockIdx.x;
    int li = blk & 1023;
    int r = li >> 7, l = li & 127;
    int grow = (l >> 5) * H_ + r * 32 + (l & 31);
    if (blk < 1024) {
        for (int k = threadIdx.x; k < 256; k += blockDim.x)
            g_whh0[(r * NLOC + l) * 256 + k] = __float2half_rn(Whh0[grow * H_ + k]);
        for (int k = threadIdx.x; k < 64; k += blockDim.x)
            g_wih0[(r * NLOC + l) * 64 + k] = __float2half_rn(Wih0[grow * I_ + k]);
        if (threadIdx.x == 0) g_bias0[r * NLOC + l] = bih0[grow] + bhh0[grow];
    } else {
        // L1 catenated row: [Whh1 row (256) | Wih1 row (256)]
        for (int k = threadIdx.x; k < 512; k += blockDim.x) {
            float v = (k < 256) ? Whh1[grow * H_ + k] : Wih1[grow * H_ + (k - 256)];
            g_w1cat[(r * NLOC + l) * 512 + k] = __float2half_rn(v);
        }
        if (threadIdx.x == 0) g_bias1[r * NLOC + l] = bih1[grow] + bhh1[grow];
    }
}

// ---------------- time-parallel L0 input GEMM: xg0[cta,t,tid,0:8] ----------------
__global__ void __launch_bounds__(256) xg_gemm64(const float* __restrict__ xin) {
    constexpr int KT  = 4;
    constexpr int KPB = (64 + 8) * 2;   // 144

    extern __shared__ __align__(16) char smem[];
    char*  sW    = smem;                     // 128 x 144
    char*  sB    = sW + NLOC * KPB;          // 16 x 144
    float* sG    = (float*)(sB + MR * KPB);  // 128 x 17
    float* sBias = sG + NLOC * 17;

    const int tid  = threadIdx.x;
    const int wid  = tid >> 5;
    const int lane = tid & 31;
    const int rank = blockIdx.x & 7;
    const int bm0  = (blockIdx.x >> 3) * MR;
    const int t0   = blockIdx.y * TCH;

    {
        const uint4* src = (const uint4*)(g_wih0 + (size_t)rank * NLOC * 64);
        for (int i = tid; i < NLOC * 8; i += 256) {
            int l = i >> 3, c = i & 7;
            *(uint4*)(sW + l * KPB + c * 16) = src[i];
        }
    }
    if (tid < NLOC) sBias[tid] = g_bias0[rank * NLOC + tid];
    __syncthreads();

    uint32_t wreg[KT][4];
    {
        unsigned rb = su32(sW) + (unsigned)(wid * 16 + (lane & 15)) * KPB + ((lane & 16) ? 16u : 0u);
#pragma unroll
        for (int kt = 0; kt < KT; kt++) ldsm_x4(wreg[kt], rb + kt * 32);
    }

    const unsigned sBu = su32(sB);
    const unsigned boffL = (unsigned)((lane & 7) * KPB) + ((lane & 8) ? 16u : 0u);
    const int gid = lane >> 2, ctid = lane & 3;
    const int m_act = tid >> 4, jj = tid & 15;
    const int mx = tid >> 4, cx = tid & 15;

    for (int tt = 0; tt < TCH; tt++) {
        const int t = t0 + tt;
        float4 v = *(const float4*)&xin[((size_t)(bm0 + mx) * T_ + t) * I_ + cx * 4];
        __half2* d = (__half2*)(sB + mx * KPB + cx * 8);
        d[0] = __floats2half2_rn(v.x, v.y);
        d[1] = __floats2half2_rn(v.z, v.w);
        __syncthreads();

        float accA[2][4] = {{0.f,0.f,0.f,0.f},{0.f,0.f,0.f,0.f}};
#pragma unroll
        for (int nt = 0; nt < 2; nt++) {
            unsigned bb = sBu + (unsigned)(nt * 8) * KPB + boffL;
#pragma unroll
            for (int kt = 0; kt < KT; kt++) {
                uint32_t b0, b1;
                ldsm_x2(b0, b1, bb + kt * 32);
                mma16816(accA[nt], wreg[kt], b0, b1);
            }
        }
#pragma unroll
        for (int nt = 0; nt < 2; nt++) {
            int col = nt * 8 + 2 * ctid;
            int row = wid * 16 + gid;
            sG[row * 17 + col]           = accA[nt][0];
            sG[row * 17 + col + 1]       = accA[nt][1];
            sG[(row + 8) * 17 + col]     = accA[nt][2];
            sG[(row + 8) * 17 + col + 1] = accA[nt][3];
        }
        __syncthreads();
        {
            int j0 = 2 * jj, j1 = j0 + 1;
            float4 oA, oB;
            oA.x = sG[(0  + j0) * 17 + m_act] + sBias[0  + j0];
            oA.y = sG[(0  + j1) * 17 + m_act] + sBias[0  + j1];
            oA.z = sG[(32 + j0) * 17 + m_act] + sBias[32 + j0];
            oA.w = sG[(32 + j1) * 17 + m_act] + sBias[32 + j1];
            oB.x = sG[(64 + j0) * 17 + m_act] + sBias[64 + j0];
            oB.y = sG[(64 + j1) * 17 + m_act] + sBias[64 + j1];
            oB.z = sG[(96 + j0) * 17 + m_act] + sBias[96 + j0];
            oB.w = sG[(96 + j1) * 17 + m_act] + sBias[96 + j1];
            size_t base = (((size_t)blockIdx.x * T_ + t) * 256 + tid) * 8;
            *(float4*)&g_xg0[base]     = oA;
            *(float4*)&g_xg0[base + 4] = oB;
        }
        __syncthreads();
    }
}

// ---------------- fused 2-layer wavefront loop ----------------
// Cluster of 8 CTAs = one batch group (16 rows). Rank r owns gate rows
// {g*256 + r*32 + j} and h-cols [r*32, r*32+32) for BOTH layers.
// Superstep s: GEMM0 gates0 = Whh0(reg) @ h0[s-1]; GEMM1 gates1 = W1cat(smem) @ [h1[s-2]|h0[s-1]].
// One __syncthreads + one cluster barrier per superstep. L1 lags L0 by one step.
// h-cat row layout (per batch row, 520 halves padded): [h1 (256) | h0 (256) | pad 8].
__global__ void __launch_bounds__(256, 1) __cluster_dims__(CSZ, 1, 1)
lstm_fused() {
    constexpr int W1B   = 1040;            // W1cat / hcat row stride bytes (520 halves)
    constexpr int HCB   = MR * W1B;        // one hcat buffer = 16640 B
    constexpr int HC_OFF = NLOC * W1B;     // 133120
    constexpr int SG0_OFF = HC_OFF + 2 * HCB;          // 166400
    constexpr int SG1_OFF = SG0_OFF + NLOC * 17 * 4;   // 175104
    constexpr int SB1_OFF = SG1_OFF + NLOC * 17 * 4;   // 183808

    extern __shared__ __align__(16) char smem[];
    char*  sW1 = smem;
    char*  sHC = smem + HC_OFF;
    float* sG0 = (float*)(smem + SG0_OFF);
    float* sG1 = (float*)(smem + SG1_OFF);
    float* sB1 = (float*)(smem + SB1_OFF);

    const int tid  = threadIdx.x;
    const int wid  = tid >> 5;
    const int lane = tid & 31;
    unsigned rank;
    asm("mov.u32 %0, %%cluster_ctarank;" : "=r"(rank));
    const int bm0 = (blockIdx.x >> 3) * MR;

    // ---- Phase A: stage Whh0 TEMPORARILY into the (unloaded) sW1 region, grab wreg0 ----
    {
        const uint4* s0 = (const uint4*)(g_whh0 + (size_t)rank * NLOC * 256);
        for (int i = tid; i < NLOC * 32; i += 256) {
            int l = i >> 5, c = i & 31;
            *(uint4*)(sW1 + l * 528 + c * 16) = s0[i];   // footprint 67584 B < 133120
        }
    }
    __syncthreads();
    uint32_t wreg0[16][4];
    {
        unsigned rb = su32(sW1) + (unsigned)(wid * 16 + (lane & 15)) * 528 + ((lane & 16) ? 16u : 0u);
#pragma unroll
        for (int kt = 0; kt < 16; kt++) ldsm_x4(wreg0[kt], rb + kt * 32);
    }
    __syncthreads();

    // ---- Phase B: load real sW1, zero hcat buffers, load sB1 (no overlaps) ----
    {
        const uint4* src = (const uint4*)(g_w1cat + (size_t)rank * NLOC * 512);
        for (int i = tid; i < NLOC * 64; i += 256) {
            int l = i >> 6, c = i & 63;
            *(uint4*)(sW1 + l * W1B + c * 16) = src[i];
        }
    }
    for (int i = tid; i < 2 * HCB / 4; i += 256) ((unsigned*)sHC)[i] = 0u;
    if (tid < NLOC) sB1[tid] = g_bias1[rank * NLOC + tid];

    const unsigned sHCu = su32(sHC);
    const unsigned sW1u = su32(sW1);
    const unsigned hoffL = (unsigned)((lane & 7) * W1B) + ((lane & 8) ? 16u : 0u);
    const unsigned arow  = (unsigned)(wid * 16 + (lane & 15)) * W1B + ((lane & 16) ? 16u : 0u);
    const int gid = lane >> 2, ctid = lane & 3;
    const int m_act = tid >> 4, jj = tid & 15;

    // DSMEM publish targets: mapa on the FULL buffer-0 address (proven pattern);
    // only the small buffer toggle (0 / 16640) is added post-mapa.
    unsigned rbx[CSZ], rbh[CSZ];
    {
        unsigned offx = sHCu + (unsigned)(m_act * W1B + 512 + (rank * 32 + 2 * jj) * 2);
        unsigned offh = sHCu + (unsigned)(m_act * W1B + (rank * 32 + 2 * jj) * 2);
#pragma unroll
        for (int rr = 0; rr < CSZ; rr++) {
            asm volatile("mapa.shared::cluster.u32 %0, %1, %2;" : "=r"(rbx[rr]) : "r"(offx), "r"(rr));
            asm volatile("mapa.shared::cluster.u32 %0, %1, %2;" : "=r"(rbh[rr]) : "r"(offh), "r"(rr));
        }
    }

    // xg0 stream
    const float4* xg4 = (const float4*)g_xg0;
    const size_t xbase = ((size_t)blockIdx.x * T_) * 512 + tid * 2;
    float4 xgA = xg4[xbase], xgB = xg4[xbase + 1];

    float c00 = 0.f, c01 = 0.f, c10 = 0.f, c11 = 0.f;

    __syncthreads();
    asm volatile("barrier.cluster.arrive.aligned;" ::: "memory");
    asm volatile("barrier.cluster.wait.aligned;" ::: "memory");

#pragma unroll 1
    for (int s = 0; s <= T_; s++) {
        const unsigned rb16 = (unsigned)((s & 1) * HCB);
        const unsigned wb16 = rb16 ^ (unsigned)HCB;
        const bool do0 = (s < T_);
        const bool do1 = (s >= 1);

        // prefetch xg[s+1]
        float4 pA, pB;
        if (do0) {
            int tn = (s + 1 < T_) ? s + 1 : s;
            pA = xg4[xbase + (size_t)tn * 512];
            pB = xg4[xbase + (size_t)tn * 512 + 1];
        }

        // ---- GEMM0: gates0 = Whh0(reg) @ h0[s-1] (x-part of hcat) ----
        if (do0) {
            float e[2][4] = {{0,0,0,0},{0,0,0,0}}, o[2][4] = {{0,0,0,0},{0,0,0,0}};
            unsigned hb = sHCu + rb16 + hoffL + 512u;
#pragma unroll
            for (int kt = 0; kt < 16; kt++) {
                uint32_t b0, b1, b2, b3;
                ldsm_x2(b0, b1, hb + kt * 32);
                ldsm_x2(b2, b3, hb + 8 * W1B + kt * 32);
                float* a0 = (kt & 1) ? o[0] : e[0];
                float* a1 = (kt & 1) ? o[1] : e[1];
                mma16816(a0, wreg0[kt], b0, b1);
                mma16816(a1, wreg0[kt], b2, b3);
            }
#pragma unroll
            for (int nt = 0; nt < 2; nt++) {
                int col = nt * 8 + 2 * ctid;
                int row = wid * 16 + gid;
                sG0[row * 17 + col]           = e[nt][0] + o[nt][0];
                sG0[row * 17 + col + 1]       = e[nt][1] + o[nt][1];
                sG0[(row + 8) * 17 + col]     = e[nt][2] + o[nt][2];
                sG0[(row + 8) * 17 + col + 1] = e[nt][3] + o[nt][3];
            }
        }

        // ---- GEMM1: gates1 = W1cat(smem) @ [h1[s-2] | h0[s-1]] ----
        if (do1) {
            float e[2][4] = {{0,0,0,0},{0,0,0,0}}, o[2][4] = {{0,0,0,0},{0,0,0,0}};
            unsigned aW = sW1u + arow;
            unsigned hb = sHCu + rb16 + hoffL;
#pragma unroll
            for (int kt = 0; kt < 32; kt++) {
                uint32_t a[4], b0, b1, b2, b3;
                ldsm_x4(a, aW + kt * 32);
                ldsm_x2(b0, b1, hb + kt * 32);
                ldsm_x2(b2, b3, hb + 8 * W1B + kt * 32);
                float* a0 = (kt & 1) ? o[0] : e[0];
                float* a1 = (kt & 1) ? o[1] : e[1];
                mma16816(a0, a, b0, b1);
                mma16816(a1, a, b2, b3);
            }
#pragma unroll
            for (int nt = 0; nt < 2; nt++) {
                int col = nt * 8 + 2 * ctid;
                int row = wid * 16 + gid;
                sG1[row * 17 + col]           = e[nt][0] + o[nt][0];
                sG1[row * 17 + col + 1]       = e[nt][1] + o[nt][1];
                sG1[(row + 8) * 17 + col]     = e[nt][2] + o[nt][2];
                sG1[(row + 8) * 17 + col + 1] = e[nt][3] + o[nt][3];
            }
        }
        __syncthreads();

        const int j0 = 2 * jj, j1 = j0 + 1;

        // ---- cell0 + h0 publish ----
        if (do0) {
            float gi0 = xgA.x + sG0[(0  + j0) * 17 + m_act];
            float gi1 = xgA.y + sG0[(0  + j1) * 17 + m_act];
            float gf0 = xgA.z + sG0[(32 + j0) * 17 + m_act];
            float gf1 = xgA.w + sG0[(32 + j1) * 17 + m_act];
            float gg0 = xgB.x + sG0[(64 + j0) * 17 + m_act];
            float gg1 = xgB.y + sG0[(64 + j1) * 17 + m_act];
            float go0 = xgB.z + sG0[(96 + j0) * 17 + m_act];
            float go1 = xgB.w + sG0[(96 + j1) * 17 + m_act];
            c00 = sigm(gf0) * c00 + sigm(gi0) * tanhap(gg0);
            float h0 = sigm(go0) * tanhap(c00);
            c01 = sigm(gf1) * c01 + sigm(gi1) * tanhap(gg1);
            float h1 = sigm(go1) * tanhap(c01);
            __half2 hp = __floats2half2_rn(h0, h1);
            unsigned hv = *(unsigned*)&hp;
#pragma unroll
            for (int rr = 0; rr < CSZ; rr++) {
                asm volatile("st.shared::cluster.u32 [%0], %1;"
                             :: "r"(rbx[rr] + wb16), "r"(hv) : "memory");
            }
            xgA = pA; xgB = pB;
        }

        // ---- cell1 + h1 publish (or final output) ----
        if (do1) {
            float gi0 = sG1[(0  + j0) * 17 + m_act] + sB1[0  + j0];
            float gi1 = sG1[(0  + j1) * 17 + m_act] + sB1[0  + j1];
            float gf0 = sG1[(32 + j0) * 17 + m_act] + sB1[32 + j0];
            float gf1 = sG1[(32 + j1) * 17 + m_act] + sB1[32 + j1];
            float gg0 = sG1[(64 + j0) * 17 + m_act] + sB1[64 + j0];
            float gg1 = sG1[(64 + j1) * 17 + m_act] + sB1[64 + j1];
            float go0 = sG1[(96 + j0) * 17 + m_act] + sB1[96 + j0];
            float go1 = sG1[(96 + j1) * 17 + m_act] + sB1[96 + j1];
            c10 = sigm(gf0) * c10 + sigm(gi0) * tanhap(gg0);
            float h0 = sigm(go0) * tanhap(c10);
            c11 = sigm(gf1) * c11 + sigm(gi1) * tanhap(gg1);
            float h1 = sigm(go1) * tanhap(c11);
            if (s < T_) {
                __half2 hp = __floats2half2_rn(h0, h1);
                unsigned hv = *(unsigned*)&hp;
#pragma unroll
                for (int rr = 0; rr < CSZ; rr++) {
                    asm volatile("st.shared::cluster.u32 [%0], %1;"
                                 :: "r"(rbh[rr] + wb16), "r"(hv) : "memory");
                }
            } else {
                g_h2last[(bm0 + m_act) * H_ + rank * 32 + j0] = h0;
                g_h2last[(bm0 + m_act) * H_ + rank * 32 + j1] = h1;
            }
        }

        if (s < T_) {
            asm volatile("barrier.cluster.arrive.aligned;" ::: "memory");
            asm volatile("barrier.cluster.wait.aligned;" ::: "memory");
        }
    }
}

// ---------------- FC head ----------------
__global__ void head_kernel(const float* __restrict__ W1, const float* __restrict__ b1,
                            const float* __restrict__ W2, const float* __restrict__ b2,
                            float* __restrict__ out) {
    __shared__ float sLast[4][H_];
    __shared__ float sZ[4][5 * H_ + 4];
    int b0 = blockIdx.x * 4, tid = threadIdx.x;
#pragma unroll
    for (int i = 0; i < 4; i++) sLast[i][tid] = g_h2last[(b0 + i) * H_ + tid];
    __syncthreads();
#pragma unroll
    for (int q = 0; q < 5; q++) {
        int j = q * 256 + tid;
        const float* wr = W1 + (size_t)j * H_;
        float a0 = 0.f, a1 = 0.f, a2 = 0.f, a3 = 0.f;
#pragma unroll 8
        for (int k = 0; k < H_; k += 4) {
            float4 w = *(const float4*)&wr[k];
            a0 += w.x * sLast[0][k] + w.y * sLast[0][k+1] + w.z * sLast[0][k+2] + w.w * sLast[0][k+3];
            a1 += w.x * sLast[1][k] + w.y * sLast[1][k+1] + w.z * sLast[1][k+2] + w.w * sLast[1][k+3];
            a2 += w.x * sLast[2][k] + w.y * sLast[2][k+1] + w.z * sLast[2][k+2] + w.w * sLast[2][k+3];
            a3 += w.x * sLast[3][k] + w.y * sLast[3][k+1] + w.z * sLast[3][k+2] + w.w * sLast[3][k+3];
        }
        float bb = b1[j];
        sZ[0][j] = a0 + bb; sZ[1][j] = a1 + bb; sZ[2][j] = a2 + bb; sZ[3][j] = a3 + bb;
    }
    __syncthreads();
    int w = tid >> 5, l = tid & 31;
#pragma unroll
    for (int pp = 0; pp < 2; pp++) {
        int p = w + pp * 8;
        int b = p >> 2, o = p & 3;
        float acc = 0.f;
        for (int i = l; i < 1280; i += 32) acc += sZ[b][i] * W2[o * 1280 + i];
#pragma unroll
        for (int s = 16; s; s >>= 1) acc += __shfl_xor_sync(0xffffffffu, acc, s);
        if (l == 0) out[(b0 + b) * 4 + o] = acc + b2[o];
    }
}

// ---------------- launch ----------------
extern "C" void kernel_launch(void* const* d_in, const int* in_sizes, int n_in,
                              void* d_out, int out_size) {
    const float* x    = (const float*)d_in[0];
    const float* Wih0 = (const float*)d_in[1];
    const float* Whh0 = (const float*)d_in[2];
    const float* bih0 = (const float*)d_in[3];
    const float* bhh0 = (const float*)d_in[4];
    const float* Wih1 = (const float*)d_in[5];
    const float* Whh1 = (const float*)d_in[6];
    const float* bih1 = (const float*)d_in[7];
    const float* bhh1 = (const float*)d_in[8];
    const float* W1   = (const float*)d_in[9];
    const float* b1   = (const float*)d_in[10];
    const float* W2   = (const float*)d_in[11];
    const float* b2   = (const float*)d_in[12];

    constexpr int SMG = NLOC * 144 + MR * 144 + (NLOC * 17 + NLOC) * 4;   // 29952
    constexpr int SMF = 184320;  // 133120 (W1cat) + 33280 (hcat x2) + 2*8704 (sG) + 512 (sB1)

    cudaFuncSetAttribute(xg_gemm64, cudaFuncAttributeMaxDynamicSharedMemorySize, SMG);
    cudaFuncSetAttribute(lstm_fused, cudaFuncAttributeMaxDynamicSharedMemorySize, SMF);

    prep_kernel<<<2048, 64>>>(Wih0, Whh0, bih0, bhh0, Wih1, Whh1, bih1, bhh1);
    xg_gemm64<<<dim3(128, T_ / TCH), 256, SMG>>>(x);
    lstm_fused<<<128, 256, SMF>>>();
    head_kernel<<<64, 256>>>(W1, b1, W2, b2, (float*)d_out);
}

// round 10
// speedup vs baseline: 1.8270x; 1.2185x over previous
#include <cuda_runtime.h>
#include <cuda_fp16.h>
#include <cstdint>
#include <cstddef>

#define B_ 256
#define T_ 512
#define H_ 256
#define I_ 64
#define CSZ 8
#define MR 16
#define NLOC 128
#define TCH 32

// ---------------- device scratch ----------------
__device__ float  g_h2last[B_ * H_];
__device__ __half g_whh0[CSZ * NLOC * 256];    // L0 recurrent weights, rank-sliced
__device__ __half g_w1cat[CSZ * NLOC * 512];   // L1 [Whh1|Wih1] rows, rank-sliced
__device__ __half g_wih0[CSZ * NLOC * 64];
__device__ float  g_bias0[CSZ * NLOC];
__device__ float  g_bias1[CSZ * NLOC];
// Precomputed L0 input-gate terms (bias folded): [cta(128), t(512), tid(256), 8]
__device__ float  g_xg0[(size_t)128 * 512 * 256 * 8];

// ---------------- helpers ----------------
__device__ __forceinline__ unsigned su32(const void* p) {
    unsigned a;
    asm("{ .reg .u64 t; cvta.to.shared.u64 t, %1; cvt.u32.u64 %0, t; }" : "=r"(a) : "l"(p));
    return a;
}
__device__ __forceinline__ float tanhap(float x) {
    float y;
    asm("tanh.approx.f32 %0, %1;" : "=f"(y) : "f"(x));
    return y;
}
__device__ __forceinline__ float sigm(float x) {
    return fmaf(tanhap(0.5f * x), 0.5f, 0.5f);
}
__device__ __forceinline__ void ldsm_x2(uint32_t& b0, uint32_t& b1, unsigned a) {
    asm volatile("ldmatrix.sync.aligned.m8n8.x2.shared.b16 {%0,%1}, [%2];"
                 : "=r"(b0), "=r"(b1) : "r"(a));
}
__device__ __forceinline__ void ldsm_x4(uint32_t* r, unsigned a) {
    asm volatile("ldmatrix.sync.aligned.m8n8.x4.shared.b16 {%0,%1,%2,%3}, [%4];"
                 : "=r"(r[0]), "=r"(r[1]), "=r"(r[2]), "=r"(r[3]) : "r"(a));
}
__device__ __forceinline__ void mma16816(float* acc, const uint32_t* a, uint32_t b0, uint32_t b1) {
    asm volatile(
        "mma.sync.aligned.m16n8k16.row.col.f32.f16.f16.f32 "
        "{%0,%1,%2,%3}, {%4,%5,%6,%7}, {%8,%9}, {%0,%1,%2,%3};"
        : "+f"(acc[0]), "+f"(acc[1]), "+f"(acc[2]), "+f"(acc[3])
        : "r"(a[0]), "r"(a[1]), "r"(a[2]), "r"(a[3]), "r"(b0), "r"(b1));
}

// ---------------- weight prep ----------------
// Local row l of rank r: gate g = l>>5, h-col = r*32 + (l&31), grow = g*256 + r*32 + (l&31).
__global__ void prep_kernel(const float* __restrict__ Wih0, const float* __restrict__ Whh0,
                            const float* __restrict__ bih0, const float* __restrict__ bhh0,
                            const float* __restrict__ Wih1, const float* __restrict__ Whh1,
                            const float* __restrict__ bih1, const float* __restrict__ bhh1) {
    int blk = blockIdx.x;
    int li = blk & 1023;
    int r = li >> 7, l = li & 127;
    int grow = (l >> 5) * H_ + r * 32 + (l & 31);
    if (blk < 1024) {
        for (int k = threadIdx.x; k < 256; k += blockDim.x)
            g_whh0[(r * NLOC + l) * 256 + k] = __float2half_rn(Whh0[grow * H_ + k]);
        for (int k = threadIdx.x; k < 64; k += blockDim.x)
            g_wih0[(r * NLOC + l) * 64 + k] = __float2half_rn(Wih0[grow * I_ + k]);
        if (threadIdx.x == 0) g_bias0[r * NLOC + l] = bih0[grow] + bhh0[grow];
    } else {
        // L1 catenated row: [Whh1 row (256) | Wih1 row (256)]
        for (int k = threadIdx.x; k < 512; k += blockDim.x) {
            float v = (k < 256) ? Whh1[grow * H_ + k] : Wih1[grow * H_ + (k - 256)];
            g_w1cat[(r * NLOC + l) * 512 + k] = __float2half_rn(v);
        }
        if (threadIdx.x == 0) g_bias1[r * NLOC + l] = bih1[grow] + bhh1[grow];
    }
}

// ---------------- time-parallel L0 input GEMM: xg0[cta,t,tid,0:8] ----------------
__global__ void __launch_bounds__(256) xg_gemm64(const float* __restrict__ xin) {
    constexpr int KT  = 4;
    constexpr int KPB = (64 + 8) * 2;   // 144

    extern __shared__ __align__(16) char smem[];
    char*  sW    = smem;                     // 128 x 144
    char*  sB    = sW + NLOC * KPB;          // 16 x 144
    float* sG    = (float*)(sB + MR * KPB);  // 128 x 17
    float* sBias = sG + NLOC * 17;

    const int tid  = threadIdx.x;
    const int wid  = tid >> 5;
    const int lane = tid & 31;
    const int rank = blockIdx.x & 7;
    const int bm0  = (blockIdx.x >> 3) * MR;
    const int t0   = blockIdx.y * TCH;

    {
        const uint4* src = (const uint4*)(g_wih0 + (size_t)rank * NLOC * 64);
        for (int i = tid; i < NLOC * 8; i += 256) {
            int l = i >> 3, c = i & 7;
            *(uint4*)(sW + l * KPB + c * 16) = src[i];
        }
    }
    if (tid < NLOC) sBias[tid] = g_bias0[rank * NLOC + tid];
    __syncthreads();

    uint32_t wreg[KT][4];
    {
        unsigned rb = su32(sW) + (unsigned)(wid * 16 + (lane & 15)) * KPB + ((lane & 16) ? 16u : 0u);
#pragma unroll
        for (int kt = 0; kt < KT; kt++) ldsm_x4(wreg[kt], rb + kt * 32);
    }

    const unsigned sBu = su32(sB);
    const unsigned boffL = (unsigned)((lane & 7) * KPB) + ((lane & 8) ? 16u : 0u);
    const int gid = lane >> 2, ctid = lane & 3;
    const int m_act = tid >> 4, jj = tid & 15;
    const int mx = tid >> 4, cx = tid & 15;

    for (int tt = 0; tt < TCH; tt++) {
        const int t = t0 + tt;
        float4 v = *(const float4*)&xin[((size_t)(bm0 + mx) * T_ + t) * I_ + cx * 4];
        __half2* d = (__half2*)(sB + mx * KPB + cx * 8);
        d[0] = __floats2half2_rn(v.x, v.y);
        d[1] = __floats2half2_rn(v.z, v.w);
        __syncthreads();

        float accA[2][4] = {{0.f,0.f,0.f,0.f},{0.f,0.f,0.f,0.f}};
#pragma unroll
        for (int nt = 0; nt < 2; nt++) {
            unsigned bb = sBu + (unsigned)(nt * 8) * KPB + boffL;
#pragma unroll
            for (int kt = 0; kt < KT; kt++) {
                uint32_t b0, b1;
                ldsm_x2(b0, b1, bb + kt * 32);
                mma16816(accA[nt], wreg[kt], b0, b1);
            }
        }
#pragma unroll
        for (int nt = 0; nt < 2; nt++) {
            int col = nt * 8 + 2 * ctid;
            int row = wid * 16 + gid;
            sG[row * 17 + col]           = accA[nt][0];
            sG[row * 17 + col + 1]       = accA[nt][1];
            sG[(row + 8) * 17 + col]     = accA[nt][2];
            sG[(row + 8) * 17 + col + 1] = accA[nt][3];
        }
        __syncthreads();
        {
            int j0 = 2 * jj, j1 = j0 + 1;
            float4 oA, oB;
            oA.x = sG[(0  + j0) * 17 + m_act] + sBias[0  + j0];
            oA.y = sG[(0  + j1) * 17 + m_act] + sBias[0  + j1];
            oA.z = sG[(32 + j0) * 17 + m_act] + sBias[32 + j0];
            oA.w = sG[(32 + j1) * 17 + m_act] + sBias[32 + j1];
            oB.x = sG[(64 + j0) * 17 + m_act] + sBias[64 + j0];
            oB.y = sG[(64 + j1) * 17 + m_act] + sBias[64 + j1];
            oB.z = sG[(96 + j0) * 17 + m_act] + sBias[96 + j0];
            oB.w = sG[(96 + j1) * 17 + m_act] + sBias[96 + j1];
            size_t base = (((size_t)blockIdx.x * T_ + t) * 256 + tid) * 8;
            *(float4*)&g_xg0[base]     = oA;
            *(float4*)&g_xg0[base + 4] = oB;
        }
        __syncthreads();
    }
}

// ---------------- fused 2-layer wavefront loop ----------------
// Cluster of 8 CTAs = one batch group (16 rows). Rank r owns gate rows
// {g*256 + r*32 + j} and h-cols [r*32, r*32+32) for BOTH layers.
// Both weight sets live in REGISTERS (wreg0: Whh0, wreg1: W1cat). Per superstep,
// ONE B-frag ldsm stream over the full hcat [h1|h0] feeds both GEMMs:
// GEMM1 uses all 32 k-tiles, GEMM0 uses k-tiles 16..31 (the h0 half).
__global__ void __launch_bounds__(256, 1) __cluster_dims__(CSZ, 1, 1)
lstm_fused() {
    constexpr int W1B   = 1040;            // W1cat / hcat row stride bytes (520 halves)
    constexpr int HCB   = MR * W1B;        // one hcat buffer = 16640 B
    constexpr int HC_OFF = NLOC * W1B;     // 133120
    constexpr int SG0_OFF = HC_OFF + 2 * HCB;          // 166400
    constexpr int SG1_OFF = SG0_OFF + NLOC * 17 * 4;   // 175104
    constexpr int SB1_OFF = SG1_OFF + NLOC * 17 * 4;   // 183808

    extern __shared__ __align__(16) char smem[];
    char*  sW1 = smem;                     // init-only staging (W1cat dies after wreg1 load)
    char*  sHC = smem + HC_OFF;
    float* sG0 = (float*)(smem + SG0_OFF);
    float* sG1 = (float*)(smem + SG1_OFF);
    float* sB1 = (float*)(smem + SB1_OFF);

    const int tid  = threadIdx.x;
    const int wid  = tid >> 5;
    const int lane = tid & 31;
    unsigned rank;
    asm("mov.u32 %0, %%cluster_ctarank;" : "=r"(rank));
    const int bm0 = (blockIdx.x >> 3) * MR;

    const unsigned arow = (unsigned)(wid * 16 + (lane & 15)) * W1B + ((lane & 16) ? 16u : 0u);

    // ---- Phase A: stage Whh0 temporarily into sW1 region, grab wreg0 ----
    {
        const uint4* s0 = (const uint4*)(g_whh0 + (size_t)rank * NLOC * 256);
        for (int i = tid; i < NLOC * 32; i += 256) {
            int l = i >> 5, c = i & 31;
            *(uint4*)(sW1 + l * 528 + c * 16) = s0[i];   // footprint 67584 B
        }
    }
    __syncthreads();
    uint32_t wreg0[16][4];
    {
        unsigned rb = su32(sW1) + (unsigned)(wid * 16 + (lane & 15)) * 528 + ((lane & 16) ? 16u : 0u);
#pragma unroll
        for (int kt = 0; kt < 16; kt++) ldsm_x4(wreg0[kt], rb + kt * 32);
    }
    __syncthreads();

    // ---- Phase B: stage W1cat into sW1, grab wreg1, then sW1 is dead ----
    {
        const uint4* src = (const uint4*)(g_w1cat + (size_t)rank * NLOC * 512);
        for (int i = tid; i < NLOC * 64; i += 256) {
            int l = i >> 6, c = i & 63;
            *(uint4*)(sW1 + l * W1B + c * 16) = src[i];
        }
    }
    __syncthreads();
    uint32_t wreg1[32][4];
    {
        unsigned aW = su32(sW1) + arow;
#pragma unroll
        for (int kt = 0; kt < 32; kt++) ldsm_x4(wreg1[kt], aW + kt * 32);
    }
    __syncthreads();

    // ---- Phase C: zero hcat buffers, load bias ----
    for (int i = tid; i < 2 * HCB / 4; i += 256) ((unsigned*)sHC)[i] = 0u;
    if (tid < NLOC) sB1[tid] = g_bias1[rank * NLOC + tid];

    const unsigned sHCu = su32(sHC);
    const unsigned hoffL = (unsigned)((lane & 7) * W1B) + ((lane & 8) ? 16u : 0u);
    const int gid = lane >> 2, ctid = lane & 3;
    const int m_act = tid >> 4, jj = tid & 15;

    // DSMEM publish base offsets (mapa done inline per publish to save registers)
    const unsigned offh = sHCu + (unsigned)(m_act * W1B + (rank * 32 + 2 * jj) * 2);  // h1 slot
    const unsigned offx = offh + 512u;                                                // h0 slot

    // xg0 stream
    const float4* xg4 = (const float4*)g_xg0;
    const size_t xbase = ((size_t)blockIdx.x * T_) * 512 + tid * 2;
    float4 xgA = xg4[xbase], xgB = xg4[xbase + 1];

    float c00 = 0.f, c01 = 0.f, c10 = 0.f, c11 = 0.f;

    __syncthreads();
    asm volatile("barrier.cluster.arrive.aligned;" ::: "memory");
    asm volatile("barrier.cluster.wait.aligned;" ::: "memory");

#pragma unroll 1
    for (int s = 0; s <= T_; s++) {
        const unsigned rb16 = (unsigned)((s & 1) * HCB);
        const unsigned wb16 = rb16 ^ (unsigned)HCB;
        const bool do0 = (s < T_);
        const bool do1 = (s >= 1);

        // prefetch xg[s+1]
        float4 pA, pB;
        if (do0) {
            int tn = (s + 1 < T_) ? s + 1 : s;
            pA = xg4[xbase + (size_t)tn * 512];
            pB = xg4[xbase + (size_t)tn * 512 + 1];
        }

        // ---- merged GEMMs: one B stream feeds both (run unconditionally; edge
        // supersteps compute one unused result, cells below are guarded) ----
#pragma unroll
        for (int nt = 0; nt < 2; nt++) {
            float a1e[4] = {0,0,0,0}, a1o[4] = {0,0,0,0};
            float a0e[4] = {0,0,0,0}, a0o[4] = {0,0,0,0};
            unsigned hb = sHCu + rb16 + hoffL + (unsigned)(nt * 8) * W1B;
#pragma unroll
            for (int kt = 0; kt < 32; kt++) {
                uint32_t b0, b1;
                ldsm_x2(b0, b1, hb + kt * 32);
                mma16816((kt & 1) ? a1o : a1e, wreg1[kt], b0, b1);
                if (kt >= 16)
                    mma16816((kt & 1) ? a0o : a0e, wreg0[kt - 16], b0, b1);
            }
            int col = nt * 8 + 2 * ctid;
            int row = wid * 16 + gid;
            sG1[row * 17 + col]           = a1e[0] + a1o[0];
            sG1[row * 17 + col + 1]       = a1e[1] + a1o[1];
            sG1[(row + 8) * 17 + col]     = a1e[2] + a1o[2];
            sG1[(row + 8) * 17 + col + 1] = a1e[3] + a1o[3];
            sG0[row * 17 + col]           = a0e[0] + a0o[0];
            sG0[row * 17 + col + 1]       = a0e[1] + a0o[1];
            sG0[(row + 8) * 17 + col]     = a0e[2] + a0o[2];
            sG0[(row + 8) * 17 + col + 1] = a0e[3] + a0o[3];
        }
        __syncthreads();

        const int j0 = 2 * jj, j1 = j0 + 1;

        // ---- cell0 + h0 publish (into h0 slot of all ranks' wbuf) ----
        if (do0) {
            float gi0 = xgA.x + sG0[(0  + j0) * 17 + m_act];
            float gi1 = xgA.y + sG0[(0  + j1) * 17 + m_act];
            float gf0 = xgA.z + sG0[(32 + j0) * 17 + m_act];
            float gf1 = xgA.w + sG0[(32 + j1) * 17 + m_act];
            float gg0 = xgB.x + sG0[(64 + j0) * 17 + m_act];
            float gg1 = xgB.y + sG0[(64 + j1) * 17 + m_act];
            float go0 = xgB.z + sG0[(96 + j0) * 17 + m_act];
            float go1 = xgB.w + sG0[(96 + j1) * 17 + m_act];
            c00 = sigm(gf0) * c00 + sigm(gi0) * tanhap(gg0);
            float h0 = sigm(go0) * tanhap(c00);
            c01 = sigm(gf1) * c01 + sigm(gi1) * tanhap(gg1);
            float h1 = sigm(go1) * tanhap(c01);
            __half2 hp = __floats2half2_rn(h0, h1);
            unsigned hv = *(unsigned*)&hp;
            const unsigned src_ = offx + wb16;
#pragma unroll
            for (int rr = 0; rr < CSZ; rr++) {
                unsigned ra;
                asm volatile("mapa.shared::cluster.u32 %0, %1, %2;" : "=r"(ra) : "r"(src_), "r"(rr));
                asm volatile("st.shared::cluster.u32 [%0], %1;" :: "r"(ra), "r"(hv) : "memory");
            }
            xgA = pA; xgB = pB;
        }

        // ---- cell1 + h1 publish (or final output) ----
        if (do1) {
            float gi0 = sG1[(0  + j0) * 17 + m_act] + sB1[0  + j0];
            float gi1 = sG1[(0  + j1) * 17 + m_act] + sB1[0  + j1];
            float gf0 = sG1[(32 + j0) * 17 + m_act] + sB1[32 + j0];
            float gf1 = sG1[(32 + j1) * 17 + m_act] + sB1[32 + j1];
            float gg0 = sG1[(64 + j0) * 17 + m_act] + sB1[64 + j0];
            float gg1 = sG1[(64 + j1) * 17 + m_act] + sB1[64 + j1];
            float go0 = sG1[(96 + j0) * 17 + m_act] + sB1[96 + j0];
            float go1 = sG1[(96 + j1) * 17 + m_act] + sB1[96 + j1];
            c10 = sigm(gf0) * c10 + sigm(gi0) * tanhap(gg0);
            float h0 = sigm(go0) * tanhap(c10);
            c11 = sigm(gf1) * c11 + sigm(gi1) * tanhap(gg1);
            float h1 = sigm(go1) * tanhap(c11);
            if (s < T_) {
                __half2 hp = __floats2half2_rn(h0, h1);
                unsigned hv = *(unsigned*)&hp;
                const unsigned src_ = offh + wb16;
#pragma unroll
                for (int rr = 0; rr < CSZ; rr++) {
                    unsigned ra;
                    asm volatile("mapa.shared::cluster.u32 %0, %1, %2;" : "=r"(ra) : "r"(src_), "r"(rr));
                    asm volatile("st.shared::cluster.u32 [%0], %1;" :: "r"(ra), "r"(hv) : "memory");
                }
            } else {
                g_h2last[(bm0 + m_act) * H_ + rank * 32 + j0] = h0;
                g_h2last[(bm0 + m_act) * H_ + rank * 32 + j1] = h1;
            }
        }

        if (s < T_) {
            asm volatile("barrier.cluster.arrive.aligned;" ::: "memory");
            asm volatile("barrier.cluster.wait.aligned;" ::: "memory");
        }
    }
}

// ---------------- FC head ----------------
__global__ void head_kernel(const float* __restrict__ W1, const float* __restrict__ b1,
                            const float* __restrict__ W2, const float* __restrict__ b2,
                            float* __restrict__ out) {
    __shared__ float sLast[4][H_];
    __shared__ float sZ[4][5 * H_ + 4];
    int b0 = blockIdx.x * 4, tid = threadIdx.x;
#pragma unroll
    for (int i = 0; i < 4; i++) sLast[i][tid] = g_h2last[(b0 + i) * H_ + tid];
    __syncthreads();
#pragma unroll
    for (int q = 0; q < 5; q++) {
        int j = q * 256 + tid;
        const float* wr = W1 + (size_t)j * H_;
        float a0 = 0.f, a1 = 0.f, a2 = 0.f, a3 = 0.f;
#pragma unroll 8
        for (int k = 0; k < H_; k += 4) {
            float4 w = *(const float4*)&wr[k];
            a0 += w.x * sLast[0][k] + w.y * sLast[0][k+1] + w.z * sLast[0][k+2] + w.w * sLast[0][k+3];
            a1 += w.x * sLast[1][k] + w.y * sLast[1][k+1] + w.z * sLast[1][k+2] + w.w * sLast[1][k+3];
            a2 += w.x * sLast[2][k] + w.y * sLast[2][k+1] + w.z * sLast[2][k+2] + w.w * sLast[2][k+3];
            a3 += w.x * sLast[3][k] + w.y * sLast[3][k+1] + w.z * sLast[3][k+2] + w.w * sLast[3][k+3];
        }
        float bb = b1[j];
        sZ[0][j] = a0 + bb; sZ[1][j] = a1 + bb; sZ[2][j] = a2 + bb; sZ[3][j] = a3 + bb;
    }
    __syncthreads();
    int w = tid >> 5, l = tid & 31;
#pragma unroll
    for (int pp = 0; pp < 2; pp++) {
        int p = w + pp * 8;
        int b = p >> 2, o = p & 3;
        float acc = 0.f;
        for (int i = l; i < 1280; i += 32) acc += sZ[b][i] * W2[o * 1280 + i];
#pragma unroll
        for (int s = 16; s; s >>= 1) acc += __shfl_xor_sync(0xffffffffu, acc, s);
        if (l == 0) out[(b0 + b) * 4 + o] = acc + b2[o];
    }
}

// ---------------- launch ----------------
extern "C" void kernel_launch(void* const* d_in, const int* in_sizes, int n_in,
                              void* d_out, int out_size) {
    const float* x    = (const float*)d_in[0];
    const float* Wih0 = (const float*)d_in[1];
    const float* Whh0 = (const float*)d_in[2];
    const float* bih0 = (const float*)d_in[3];
    const float* bhh0 = (const float*)d_in[4];
    const float* Wih1 = (const float*)d_in[5];
    const float* Whh1 = (const float*)d_in[6];
    const float* bih1 = (const float*)d_in[7];
    const float* bhh1 = (const float*)d_in[8];
    const float* W1   = (const float*)d_in[9];
    const float* b1   = (const float*)d_in[10];
    const float* W2   = (const float*)d_in[11];
    const float* b2   = (const float*)d_in[12];

    constexpr int SMG = NLOC * 144 + MR * 144 + (NLOC * 17 + NLOC) * 4;   // 29952
    constexpr int SMF = 184320;

    cudaFuncSetAttribute(xg_gemm64, cudaFuncAttributeMaxDynamicSharedMemorySize, SMG);
    cudaFuncSetAttribute(lstm_fused, cudaFuncAttributeMaxDynamicSharedMemorySize, SMF);

    prep_kernel<<<2048, 64>>>(Wih0, Whh0, bih0, bhh0, Wih1, Whh1, bih1, bhh1);
    xg_gemm64<<<dim3(128, T_ / TCH), 256, SMG>>>(x);
    lstm_fused<<<128, 256, SMF>>>();
    head_kernel<<<64, 256>>>(W1, b1, W2, b2, (float*)d_out);
}